// round 9
// baseline (speedup 1.0000x reference)
#include <cuda_runtime.h>
#include <cuda_bf16.h>
#include <math_constants.h>
#include <cstdint>

#define M_ROWS 32768
#define DIMS   256
#define NCODES 1024
#define NCAND  8
#define MARGIN 2.5e-4f

#if defined(__CUDA_ARCH_FEAT_SM103_ALL) || defined(__CUDA_ARCH_FEAT_SM100_ALL) || defined(__CUDA_ARCH_FEAT_SM101_ALL)
#define HAS_TC 1
#else
#define HAS_TC 0
#endif

// ---------------- device-global scratch ------------------------------------
__device__ float g_z[M_ROWS * DIMS];
__device__ __align__(16) __nv_bfloat16 g_wh[DIMS * DIMS];
__device__ __align__(16) __nv_bfloat16 g_wm[DIMS * DIMS];
__device__ __align__(16) __nv_bfloat16 g_wl[DIMS * DIMS];
__device__ __align__(16) __nv_bfloat16 g_eh[NCODES * DIMS];
__device__ __align__(16) __nv_bfloat16 g_el[NCODES * DIMS];
__device__ float g_cnorm[NCODES];
__device__ float g_rownorm[M_ROWS];
__device__ int   g_idx[M_ROWS];
__device__ float g_rowloss[M_ROWS];
__device__ int   g_cands[M_ROWS * NCAND];
__device__ int   g_ccount[M_ROWS];

// ---------------- PTX helpers ------------------------------------------------
__device__ __forceinline__ uint32_t smem_u32(const void* p) {
    uint32_t a;
    asm("{ .reg .u64 t; cvta.to.shared.u64 t, %1; cvt.u32.u64 %0, t; }" : "=r"(a) : "l"(p));
    return a;
}
#define CP_ASYNC16(s, g) asm volatile("cp.async.cg.shared.global [%0], [%1], 16;" :: "r"(s), "l"(g) : "memory")
#define CP_COMMIT()      asm volatile("cp.async.commit_group;" ::: "memory")
#define CP_WAIT0()       asm volatile("cp.async.wait_group 0;" ::: "memory")
#define FENCE_ASYNC()    asm volatile("fence.proxy.async.shared::cta;" ::: "memory")
#define MBAR_INIT(mb, c) asm volatile("mbarrier.init.shared.b64 [%0], %1;" :: "r"(mb), "r"(c) : "memory")
#define MBAR_INVAL(mb)   asm volatile("mbarrier.inval.shared.b64 [%0];" :: "r"(mb) : "memory")
#define MBAR_WAIT(mb, ph) do {                                                 \
    uint32_t _m = (mb), _p = (ph), _d;                                         \
    asm volatile("{\n\t.reg .pred p;\n\t"                                      \
        "mbarrier.try_wait.parity.acquire.cta.shared::cta.b64 p, [%1], %2;\n\t"\
        "selp.b32 %0, 1, 0, p;\n\t}" : "=r"(_d) : "r"(_m), "r"(_p) : "memory");\
    if (!_d) {                                                                 \
        asm volatile("{\n\t.reg .pred P1;\n\tWL_%=:\n\t"                       \
            "mbarrier.try_wait.parity.acquire.cta.shared::cta.b64 P1, [%0], %1, 0x989680;\n\t" \
            "@P1 bra.uni WD_%=;\n\tbra.uni WL_%=;\n\tWD_%=:\n\t}"              \
            :: "r"(_m), "r"(_p) : "memory");                                   \
    }                                                                          \
} while (0)

#if HAS_TC
__device__ __forceinline__ uint32_t elect_one() {
    uint32_t p;
    asm volatile("{\n\t.reg .pred p;\n\telect.sync _|p, 0xFFFFFFFF;\n\t"
                 "selp.b32 %0, 1, 0, p;\n\t}" : "=r"(p));
    return p;
}
#define TC_ALLOC(sa, n)  asm volatile("tcgen05.alloc.cta_group::1.sync.aligned.shared::cta.b32 [%0], %1;" :: "r"(sa), "r"(n) : "memory")
#define TC_RELINQ()      asm volatile("tcgen05.relinquish_alloc_permit.cta_group::1.sync.aligned;")
#define TC_DEALLOC(t, n) asm volatile("tcgen05.dealloc.cta_group::1.sync.aligned.b32 %0, %1;" :: "r"(t), "r"(n))
#define TC_COMMIT(mb)    asm volatile("tcgen05.commit.cta_group::1.mbarrier::arrive::one.shared::cluster.b64 [%0];" :: "r"(mb) : "memory")
#define TC_WAIT_LD()     asm volatile("tcgen05.wait::ld.sync.aligned;" ::: "memory")
#define TC_WAIT_ST()     asm volatile("tcgen05.wait::st.sync.aligned;" ::: "memory")
#define TC_FENCE_B()     asm volatile("tcgen05.fence::before_thread_sync;" ::: "memory")
#define TC_FENCE_A()     asm volatile("tcgen05.fence::after_thread_sync;" ::: "memory")

static constexpr uint64_t DESC_SW128 =
    (uint64_t(2) << 61) | (uint64_t(1) << 46) | (uint64_t(64) << 32) | (uint64_t(1) << 16);
__device__ __forceinline__ uint64_t make_desc(uint32_t a) {
    return DESC_SW128 | ((uint64_t)(a >> 4) & 0x3FFF);
}
__device__ __forceinline__ void mma_f16_ts(uint32_t d, uint32_t a, uint64_t b,
                                           uint32_t idesc, bool en) {
    uint32_t e = en ? 1u : 0u, z = 0u;
    asm volatile("{\n\t.reg .pred p;\n\tsetp.ne.u32 p, %5, 0;\n\t"
        "tcgen05.mma.cta_group::1.kind::f16 [%0], [%1], %2, %3, {%4, %4, %4, %4}, p;\n\t}"
        :: "r"(d), "r"(a), "l"(b), "r"(idesc), "r"(z), "r"(e) : "memory");
}
__device__ __forceinline__ void mma_f16_ss(uint32_t d, uint64_t a, uint64_t b,
                                           uint32_t idesc, bool en) {
    uint32_t e = en ? 1u : 0u, z = 0u;
    asm volatile("{\n\t.reg .pred p;\n\tsetp.ne.u32 p, %5, 0;\n\t"
        "tcgen05.mma.cta_group::1.kind::f16 [%0], %1, %2, %3, {%4, %4, %4, %4}, p;\n\t}"
        :: "r"(d), "l"(a), "l"(b), "r"(idesc), "r"(z), "r"(e) : "memory");
}
__device__ __forceinline__ void ldtm32(uint32_t* r, uint32_t a) {
    asm volatile("tcgen05.ld.sync.aligned.32x32b.x32.b32 "
        "{%0,%1,%2,%3,%4,%5,%6,%7,%8,%9,%10,%11,%12,%13,%14,%15,"
        "%16,%17,%18,%19,%20,%21,%22,%23,%24,%25,%26,%27,%28,%29,%30,%31}, [%32];"
        : "=r"(r[0]),"=r"(r[1]),"=r"(r[2]),"=r"(r[3]),"=r"(r[4]),"=r"(r[5]),
          "=r"(r[6]),"=r"(r[7]),"=r"(r[8]),"=r"(r[9]),"=r"(r[10]),"=r"(r[11]),
          "=r"(r[12]),"=r"(r[13]),"=r"(r[14]),"=r"(r[15]),"=r"(r[16]),"=r"(r[17]),
          "=r"(r[18]),"=r"(r[19]),"=r"(r[20]),"=r"(r[21]),"=r"(r[22]),"=r"(r[23]),
          "=r"(r[24]),"=r"(r[25]),"=r"(r[26]),"=r"(r[27]),"=r"(r[28]),"=r"(r[29]),
          "=r"(r[30]),"=r"(r[31]) : "r"(a));
}
__device__ __forceinline__ void sttm32(uint32_t a, const uint32_t* r) {
    asm volatile("tcgen05.st.sync.aligned.32x32b.x32.b32 [%0], "
        "{%1,%2,%3,%4,%5,%6,%7,%8,%9,%10,%11,%12,%13,%14,%15,%16,"
        "%17,%18,%19,%20,%21,%22,%23,%24,%25,%26,%27,%28,%29,%30,%31,%32};"
        :: "r"(a),
           "r"(r[0]),"r"(r[1]),"r"(r[2]),"r"(r[3]),"r"(r[4]),"r"(r[5]),
           "r"(r[6]),"r"(r[7]),"r"(r[8]),"r"(r[9]),"r"(r[10]),"r"(r[11]),
           "r"(r[12]),"r"(r[13]),"r"(r[14]),"r"(r[15]),"r"(r[16]),"r"(r[17]),
           "r"(r[18]),"r"(r[19]),"r"(r[20]),"r"(r[21]),"r"(r[22]),"r"(r[23]),
           "r"(r[24]),"r"(r[25]),"r"(r[26]),"r"(r[27]),"r"(r[28]),"r"(r[29]),
           "r"(r[30]),"r"(r[31]) : "memory");
}
static constexpr uint32_t MMA_IDESC =   // coarse: N=64
    (1u << 4) | (1u << 7) | (1u << 10) | (8u << 17) | (8u << 24);
static constexpr uint32_t IDESC_G =     // gemm: N=256
    (1u << 4) | (1u << 7) | (1u << 10) | (32u << 17) | (8u << 24);
#endif // HAS_TC

__device__ __forceinline__ void split3(float a, __nv_bfloat16& h, __nv_bfloat16& m,
                                       __nv_bfloat16& l) {
    h = __float2bfloat16(a);
    float r = a - __bfloat162float(h);
    m = __float2bfloat16(r);
    l = __float2bfloat16(r - __bfloat162float(m));
}
__device__ __forceinline__ uint32_t toff(int r, int k) {
    uint32_t lin = (uint32_t)(r >> 3) * 1024u + (uint32_t)(k >> 6) * 8192u
                 + (uint32_t)(r & 7) * 128u + (uint32_t)(k & 63) * 2u;
    return lin ^ ((lin >> 3) & 0x70u);
}
// top-3 tracker: values m1<=m2<=m3, indices for first two (first-index on ties)
__device__ __forceinline__ void top3_upd(float d, int col, float& m1, int& i1,
                                         float& m2, int& i2, float& m3) {
    if (d < m1)      { m3 = m2; m2 = m1; i2 = i1; m1 = d; i1 = col; }
    else if (d < m2) { m3 = m2; m2 = d; i2 = col; }
    else if (d < m3) { m3 = d; }
}

// ---------------- K0: W -> 3-way bf16 split ---------------------------------
__global__ void conv_w_kernel(const float* __restrict__ W)
{
    size_t base = ((size_t)blockIdx.x * 256 + threadIdx.x) * 8;
    float v[8];
    *reinterpret_cast<float4*>(v)     = *reinterpret_cast<const float4*>(W + base);
    *reinterpret_cast<float4*>(v + 4) = *reinterpret_cast<const float4*>(W + base + 4);
    __nv_bfloat16 h[8], m[8], l[8];
#pragma unroll
    for (int j = 0; j < 8; j++) split3(v[j], h[j], m[j], l[j]);
    *reinterpret_cast<uint4*>(&g_wh[base]) = *reinterpret_cast<uint4*>(h);
    *reinterpret_cast<uint4*>(&g_wm[base]) = *reinterpret_cast<uint4*>(m);
    *reinterpret_cast<uint4*>(&g_wl[base]) = *reinterpret_cast<uint4*>(l);
}

// ---------------- K1: z = x @ W^T + b  (tcgen05, 3-split bf16) ---------------
static constexpr uint32_t G_A = 0;
static constexpr uint32_t G_B = 98304;
static constexpr uint32_t G_BIAS = 196608;
static constexpr uint32_t G_MB = 197632, G_TP = 197640;
static constexpr uint32_t GSMEM_NEED = 197644 + 1040;

__global__ __launch_bounds__(256, 1)
void gemm_z_tc(const float* __restrict__ x, const float* __restrict__ W,
               const float* __restrict__ bias)
{
#if HAS_TC
    extern __shared__ char smraw[];
    uint32_t raw = smem_u32(smraw);
    uint32_t sb  = (raw + 1023u) & ~1023u;
    char* sm = smraw + (sb - raw);
    float* sbias = reinterpret_cast<float*>(sm + G_BIAS);

    const int tid = threadIdx.x;
    const int rb  = blockIdx.x * 128;

    if (tid < 32) TC_ALLOC(sb + G_TP, 256);
    if (tid == 0) MBAR_INIT(sb + G_MB, 1);
    sbias[tid] = bias[tid];
    __syncthreads();
    uint32_t tmem;
    asm volatile("ld.shared.b32 %0, [%1];" : "=r"(tmem) : "r"(sb + G_TP));

#pragma unroll
    for (int g = tid; g < 1024; g += 256) {
        int r = g >> 3, k8 = (g & 7) << 3;
        const float* src = x + (size_t)(rb + r) * DIMS + k8;
        float v[8];
        *reinterpret_cast<float4*>(v)     = *reinterpret_cast<const float4*>(src);
        *reinterpret_cast<float4*>(v + 4) = *reinterpret_cast<const float4*>(src + 4);
        __nv_bfloat16 h[8], m[8], l[8];
#pragma unroll
        for (int j = 0; j < 8; j++) split3(v[j], h[j], m[j], l[j]);
        uint32_t o = toff(r, k8);
        *reinterpret_cast<uint4*>(sm + G_A + o)         = *reinterpret_cast<uint4*>(h);
        *reinterpret_cast<uint4*>(sm + G_A + 16384 + o) = *reinterpret_cast<uint4*>(m);
        *reinterpret_cast<uint4*>(sm + G_A + 32768 + o) = *reinterpret_cast<uint4*>(l);
    }
    FENCE_ASYNC();

    for (int ch = 0; ch < 4; ++ch) {
        for (int c = tid; c < 6144; c += 256) {
            int s = c >> 11, ci = c & 2047;
            int r = ci >> 3, k8 = (ci & 7) << 3;
            const __nv_bfloat16* src =
                (s == 0 ? g_wh : s == 1 ? g_wm : g_wl) + (size_t)r * DIMS + ch * 64 + k8;
            CP_ASYNC16(sb + G_B + (uint32_t)s * 32768u + toff(r, k8), src);
        }
        CP_COMMIT(); CP_WAIT0();
        __syncthreads();

        if (tid < 32 && elect_one()) {
            TC_FENCE_A();
            uint64_t A0 = make_desc(sb + G_A + (uint32_t)(ch & 1) * 49152u);
            uint64_t A1 = A0 + 1024, A2 = A0 + 2048;
            uint64_t B0 = make_desc(sb + G_B);
            uint64_t B1 = B0 + 2048, B2 = B0 + 4096;
#pragma unroll
            for (int kk = 0; kk < 4; ++kk) {
                uint64_t off = (uint64_t)(kk * 2);
                mma_f16_ss(tmem, A0 + off, B0 + off, IDESC_G, !(ch == 0 && kk == 0));
                mma_f16_ss(tmem, A0 + off, B1 + off, IDESC_G, true);
                mma_f16_ss(tmem, A1 + off, B0 + off, IDESC_G, true);
                mma_f16_ss(tmem, A1 + off, B1 + off, IDESC_G, true);
                mma_f16_ss(tmem, A0 + off, B2 + off, IDESC_G, true);
                mma_f16_ss(tmem, A2 + off, B0 + off, IDESC_G, true);
            }
            TC_COMMIT(sb + G_MB);
        }
        if (ch < 3) {
            uint32_t abase = G_A + (uint32_t)((ch + 1) & 1) * 49152u;
#pragma unroll
            for (int g = tid; g < 1024; g += 256) {
                int r = g >> 3, k8 = (g & 7) << 3;
                const float* src = x + (size_t)(rb + r) * DIMS + (ch + 1) * 64 + k8;
                float v[8];
                *reinterpret_cast<float4*>(v)     = *reinterpret_cast<const float4*>(src);
                *reinterpret_cast<float4*>(v + 4) = *reinterpret_cast<const float4*>(src + 4);
                __nv_bfloat16 h[8], m[8], l[8];
#pragma unroll
                for (int j = 0; j < 8; j++) split3(v[j], h[j], m[j], l[j]);
                uint32_t o = toff(r, k8);
                *reinterpret_cast<uint4*>(sm + abase + o)         = *reinterpret_cast<uint4*>(h);
                *reinterpret_cast<uint4*>(sm + abase + 16384 + o) = *reinterpret_cast<uint4*>(m);
                *reinterpret_cast<uint4*>(sm + abase + 32768 + o) = *reinterpret_cast<uint4*>(l);
            }
            FENCE_ASYNC();
        }
        MBAR_WAIT(sb + G_MB, ch & 1);
        __syncthreads();
    }
    TC_FENCE_A();

    const int sub = (tid >> 5) & 3, half = tid >> 7, lane = tid & 31;
    const int row = rb + sub * 32 + lane;
    const uint32_t woff = ((uint32_t)sub) << 21;
#pragma unroll
    for (int q = 0; q < 4; ++q) {
        uint32_t regs[32];
        ldtm32(regs, tmem + half * 128 + q * 32 + woff);
        TC_WAIT_LD();
        int c0 = half * 128 + q * 32;
#pragma unroll
        for (int j = 0; j < 32; j += 4) {
            float4 v;
            v.x = __uint_as_float(regs[j+0]) + sbias[c0+j+0];
            v.y = __uint_as_float(regs[j+1]) + sbias[c0+j+1];
            v.z = __uint_as_float(regs[j+2]) + sbias[c0+j+2];
            v.w = __uint_as_float(regs[j+3]) + sbias[c0+j+3];
            *reinterpret_cast<float4*>(&g_z[(size_t)row * DIMS + c0 + j]) = v;
        }
    }
    TC_FENCE_B();
    __syncthreads();
    if (tid == 0) MBAR_INVAL(sb + G_MB);
    __syncthreads();
    if (tid < 32) { TC_RELINQ(); TC_DEALLOC(tmem, 256); }
#else
    int tid = threadIdx.x, rb = blockIdx.x * 128;
    for (int o = tid; o < 128 * DIMS; o += 256) {
        int r = rb + (o >> 8), c = o & 255;
        float acc = 0.f;
        for (int k = 0; k < DIMS; k++)
            acc += x[(size_t)r * DIMS + k] * W[(size_t)c * DIMS + k];
        g_z[(size_t)r * DIMS + c] = acc + bias[c];
    }
#endif
}

// ---------------- K2: emb -> split bf16 + code norms -------------------------
__global__ void conv_emb_kernel(const float* __restrict__ emb)
{
    int row = blockIdx.x * 8 + (threadIdx.x >> 5);
    int lane = threadIdx.x & 31;
    const float* p = &emb[(size_t)row * DIMS + lane * 8];
    float v[8];
    *reinterpret_cast<float4*>(v)     = *reinterpret_cast<const float4*>(p);
    *reinterpret_cast<float4*>(v + 4) = *reinterpret_cast<const float4*>(p + 4);
    uint4 oh, ol;
    uint32_t* ohp = reinterpret_cast<uint32_t*>(&oh);
    uint32_t* olp = reinterpret_cast<uint32_t*>(&ol);
    float s = 0.f;
#pragma unroll
    for (int j = 0; j < 4; j++) {
        float a0 = v[2*j], a1 = v[2*j+1];
        __nv_bfloat16 h0 = __float2bfloat16(a0), h1 = __float2bfloat16(a1);
        float r0 = a0 - __bfloat162float(h0), r1 = a1 - __bfloat162float(h1);
        __nv_bfloat162 hp; hp.x = h0; hp.y = h1;
        __nv_bfloat162 lp = __floats2bfloat162_rn(r0, r1);
        ohp[j] = *reinterpret_cast<uint32_t*>(&hp);
        olp[j] = *reinterpret_cast<uint32_t*>(&lp);
        s += a0*a0 + a1*a1;
    }
    *reinterpret_cast<uint4*>(&g_eh[(size_t)row * DIMS + lane * 8]) = oh;
    *reinterpret_cast<uint4*>(&g_el[(size_t)row * DIMS + lane * 8]) = ol;
#pragma unroll
    for (int ofs = 16; ofs > 0; ofs >>= 1) s += __shfl_down_sync(0xffffffffu, s, ofs);
    if (lane == 0) g_cnorm[row] = s;
}

// ---------------- K3: split-bf16 tcgen05 coarse argmin (top-3 epilogue) ------
static constexpr uint32_t S_B = 0, S_CN = 131072, S_MB = 135168, S_TP = 135184;
static constexpr uint32_t SMEM_NEED = 135188 + 1024 + 12;

#if HAS_TC
__device__ __forceinline__ void load_btile_async(uint32_t sbase, int tile,
                                                 int t, int nth)
{
    const __nv_bfloat16* eh = g_eh + (size_t)tile * 64 * DIMS;
    const __nv_bfloat16* el = g_el + (size_t)tile * 64 * DIMS;
    for (int c = t; c < 4096; c += nth) {
        int part = c >> 11;
        int ci = c & 2047;
        int r = ci >> 5, k = (ci & 31) << 3;
        const __nv_bfloat16* src = (part ? el : eh) + r * DIMS + k;
        CP_ASYNC16(sbase + (uint32_t)part * 32768u + toff(r, k), src);
    }
}
#endif

__global__ __launch_bounds__(256, 1)
void coarse_kernel()
{
#if HAS_TC
    extern __shared__ char smraw[];
    uint32_t raw = smem_u32(smraw);
    uint32_t sb  = (raw + 1023u) & ~1023u;
    char* sm = smraw + (sb - raw);
    float* scn = reinterpret_cast<float*>(sm + S_CN);

    const int tid = threadIdx.x;
    const int w = tid >> 5, lane = tid & 31;
    const int sub = w & 3, half = w >> 2;
    const int rb = blockIdx.x * 128;
    const int myrow = sub * 32 + lane;
    const int rowg = rb + myrow;
    const uint32_t woff = ((uint32_t)sub) << 21;

    if (w == 0) TC_ALLOC(sb + S_TP, 512);
    if (tid == 0) { MBAR_INIT(sb + S_MB, 1); MBAR_INIT(sb + S_MB + 8, 1); }
#pragma unroll
    for (int i = tid; i < NCODES; i += 256) scn[i] = g_cnorm[i];
    __syncthreads();
    uint32_t tmem;
    asm volatile("ld.shared.b32 %0, [%1];" : "=r"(tmem) : "r"(sb + S_TP));

    float rn = 0.f;
    if (half == 0) {
        const float* zp = &g_z[(size_t)rowg * DIMS];
#pragma unroll
        for (int ch = 0; ch < 4; ++ch) {
            float v[64];
#pragma unroll
            for (int q = 0; q < 16; ++q)
                *reinterpret_cast<float4*>(v + q * 4) =
                    *reinterpret_cast<const float4*>(zp + ch * 64 + q * 4);
            uint32_t hi[32], lo[32];
#pragma unroll
            for (int j = 0; j < 32; ++j) {
                float a0 = v[2*j], a1 = v[2*j+1];
                rn += a0*a0 + a1*a1;
                __nv_bfloat16 h0 = __float2bfloat16(a0), h1 = __float2bfloat16(a1);
                float r0 = a0 - __bfloat162float(h0), r1 = a1 - __bfloat162float(h1);
                __nv_bfloat162 hp; hp.x = h0; hp.y = h1;
                __nv_bfloat162 lp = __floats2bfloat162_rn(r0, r1);
                hi[j] = *reinterpret_cast<uint32_t*>(&hp);
                lo[j] = *reinterpret_cast<uint32_t*>(&lp);
            }
            sttm32(tmem +       ch * 32 + woff, hi);
            sttm32(tmem + 128 + ch * 32 + woff, lo);
        }
        TC_WAIT_ST();
        TC_FENCE_B();
        g_rownorm[rowg] = rn;
    } else {
        load_btile_async(sb + S_B, 0, tid - 128, 128);
        CP_COMMIT();
    }
    __syncthreads();
    if (half == 1) rn = g_rownorm[rowg];

    float m1 = CUDART_INF_F, m2 = CUDART_INF_F, m3 = CUDART_INF_F;
    int i1 = 0, i2 = 0;

    for (int i = 0; i < 16; ++i) {
        const int buf = i & 1;
        CP_WAIT0();
        __syncthreads();
        if (w == 0 && elect_one()) {
            TC_FENCE_A();
            uint64_t bh = make_desc(sb + S_B + (uint32_t)buf * 65536u);
            uint64_t bl = bh + 2048;
            uint32_t D  = tmem + 256 + buf * 64;
#pragma unroll
            for (int c = 0; c < 16; ++c) {
                uint64_t off = (uint64_t)((c >> 2) * 512 + (c & 3) * 2);
                uint32_t ah = tmem + c * 8, al = tmem + 128 + c * 8;
                mma_f16_ts(D, ah, bh + off, MMA_IDESC, c > 0);
                mma_f16_ts(D, ah, bl + off, MMA_IDESC, true);
                mma_f16_ts(D, al, bh + off, MMA_IDESC, true);
            }
            TC_COMMIT(sb + S_MB + 8 * buf);
        }
        if (i >= 1) { MBAR_WAIT(sb + S_MB + 8 * (buf ^ 1), ((i - 1) >> 1) & 1); TC_FENCE_A(); }
        if (i < 15) { load_btile_async(sb + S_B + (uint32_t)(buf ^ 1) * 65536u, i + 1, tid, 256); CP_COMMIT(); }
        if (i >= 1) {
            uint32_t regs[32];
            ldtm32(regs, tmem + 256 + (buf ^ 1) * 64 + (half << 5) + woff);
            TC_WAIT_LD();
            const int col0 = (i - 1) * 64 + (half << 5);
#pragma unroll
            for (int r = 0; r < 32; ++r) {
                int col = col0 + r;
                float d = __fadd_rn(rn, scn[col]) - 2.0f * __uint_as_float(regs[r]);
                top3_upd(d, col, m1, i1, m2, i2, m3);
            }
            TC_FENCE_B();
        }
    }
    MBAR_WAIT(sb + S_MB + 8, 1);
    TC_FENCE_A();
    {
        uint32_t regs[32];
        ldtm32(regs, tmem + 256 + 64 + (half << 5) + woff);
        TC_WAIT_LD();
        const int col0 = 15 * 64 + (half << 5);
#pragma unroll
        for (int r = 0; r < 32; ++r) {
            int col = col0 + r;
            float d = __fadd_rn(rn, scn[col]) - 2.0f * __uint_as_float(regs[r]);
            top3_upd(d, col, m1, i1, m2, i2, m3);
        }
    }
    TC_FENCE_B();

    // ---- merge halves: each half writes (m1,i1,m2,i2,m3) -> 8 floats/slot ---
    {
        float* blk = reinterpret_cast<float*>(sm + S_B) + (myrow * 2 + half) * 8;
        blk[0] = m1;
        reinterpret_cast<int*>(blk)[1] = i1;
        blk[2] = m2;
        reinterpret_cast<int*>(blk)[3] = i2;
        blk[4] = m3;
    }
    __syncthreads();
    if (half == 0) {
        float* A = reinterpret_cast<float*>(sm + S_B) + (myrow * 2) * 8;
        float* B = A + 8;
        float av[3] = { A[0], A[2], A[4] };
        int   ai[3] = { reinterpret_cast<int*>(A)[1], reinterpret_cast<int*>(A)[3], 0x7fffffff };
        float bv[3] = { B[0], B[2], B[4] };
        int   bi[3] = { reinterpret_cast<int*>(B)[1], reinterpret_cast<int*>(B)[3], 0x7fffffff };
        float gm[3]; int gi[3];
        int pa = 0, pb = 0;
#pragma unroll
        for (int t = 0; t < 3; ++t) {
            bool takeB = (bv[pb] < av[pa]) || (bv[pb] == av[pa] && bi[pb] < ai[pa]);
            if (takeB) { gm[t] = bv[pb]; gi[t] = bi[pb]; pb++; }
            else       { gm[t] = av[pa]; gi[t] = ai[pa]; pa++; }
        }
        g_idx[rowg] = gi[0];
        if (gm[1] > gm[0] + MARGIN) {
            g_ccount[rowg] = 0;                 // decided
        } else if (gm[2] > gm[0] + MARGIN) {
            g_cands[(size_t)rowg * NCAND + 0] = gi[0];
            g_cands[(size_t)rowg * NCAND + 1] = gi[1];
            g_ccount[rowg] = 2;                 // recheck the pair
        } else {
            g_ccount[rowg] = -1;                // rare: full scan
        }
    }
    __syncthreads();
    if (tid == 0) { MBAR_INVAL(sb + S_MB); MBAR_INVAL(sb + S_MB + 8); }
    __syncthreads();
    if (w == 0) { TC_RELINQ(); TC_DEALLOC(tmem, 512); }
#else
    int r = blockIdx.x * 128 + (int)threadIdx.x;
    if (threadIdx.x < 128) {
        float s = 0.f;
        for (int i = 0; i < DIMS; i++) { float v = g_z[(size_t)r * DIMS + i]; s += v * v; }
        g_rownorm[r] = s;
        g_idx[r] = 0;
        g_ccount[r] = -1;
    }
#endif
}

// ---------------- K4: exact fp32 recheck --------------------------------------
__global__ __launch_bounds__(256)
void recheck_kernel(const float* __restrict__ emb)
{
    int row  = blockIdx.x * 8 + (threadIdx.x >> 5);
    int lane = threadIdx.x & 31;
    int cnt  = g_ccount[row];
    if (cnt == 0) return;

    const float* zp = &g_z[(size_t)row * DIMS];
    float zv[8];
#pragma unroll
    for (int i = 0; i < 8; i++) zv[i] = zp[lane + 32 * i];
    float rn = g_rownorm[row];

    float bv = CUDART_INF_F;
    int   bi = 0x7fffffff;
    if (cnt > 0) {
        for (int c = 0; c < cnt; c++) {
            int idx = g_cands[(size_t)row * NCAND + c];
            const float* ep = &emb[(size_t)idx * DIMS];
            float dot = 0.f;
#pragma unroll
            for (int i = 0; i < 8; i++) dot += zv[i] * ep[lane + 32 * i];
#pragma unroll
            for (int o = 16; o > 0; o >>= 1) dot += __shfl_down_sync(0xffffffffu, dot, o);
            if (lane == 0) {
                float t = __fadd_rn(rn, g_cnorm[idx]);
                float dist = __fadd_rn(t, -__fmul_rn(2.0f, dot));
                if (dist < bv || (dist == bv && idx < bi)) { bv = dist; bi = idx; }
            }
        }
    } else {
        for (int idx = 0; idx < NCODES; idx++) {
            const float* ep = &emb[(size_t)idx * DIMS];
            float dot = 0.f;
#pragma unroll
            for (int i = 0; i < 8; i++) dot += zv[i] * ep[lane + 32 * i];
#pragma unroll
            for (int o = 16; o > 0; o >>= 1) dot += __shfl_down_sync(0xffffffffu, dot, o);
            if (lane == 0) {
                float t = __fadd_rn(rn, g_cnorm[idx]);
                float dist = __fadd_rn(t, -__fmul_rn(2.0f, dot));
                if (dist < bv) { bv = dist; bi = idx; }
            }
        }
    }
    if (lane == 0) g_idx[row] = bi;
}

// ---------------- K5: gather + per-row loss -----------------------------------
__global__ void gather_kernel(const float* __restrict__ emb,
                              float* __restrict__ outq, float* __restrict__ outi)
{
    __shared__ float ws[8];
    int row = blockIdx.x, d = threadIdx.x;
    int idx = g_idx[row];
    float e = emb[(size_t)idx * DIMS + d];
    float z = g_z[(size_t)row * DIMS + d];
    outq[(size_t)row * DIMS + d] = e;
    float diff = e - z;
    float s = diff * diff;
#pragma unroll
    for (int o = 16; o > 0; o >>= 1) s += __shfl_down_sync(0xffffffffu, s, o);
    int lane = d & 31, w = d >> 5;
    if (lane == 0) ws[w] = s;
    __syncthreads();
    if (d == 0) {
        float tot = 0.f;
#pragma unroll
        for (int i = 0; i < 8; i++) tot += ws[i];
        g_rowloss[row] = tot;
        outi[row] = (float)idx;
    }
}

// ---------------- K6: loss reduction ------------------------------------------
__global__ void loss_kernel(float* __restrict__ outl)
{
    __shared__ double sd[256];
    double s = 0.0;
    for (int i = threadIdx.x; i < M_ROWS; i += 256) s += (double)g_rowloss[i];
    sd[threadIdx.x] = s;
    __syncthreads();
    for (int o = 128; o > 0; o >>= 1) {
        if (threadIdx.x < o) sd[threadIdx.x] += sd[threadIdx.x + o];
        __syncthreads();
    }
    if (threadIdx.x == 0) outl[0] = (float)(1.25 * sd[0] / 8388608.0);
}

// ---------------- launch --------------------------------------------------------
extern "C" void kernel_launch(void* const* d_in, const int* in_sizes, int n_in,
                              void* d_out, int out_size)
{
    const float* x   = (const float*)d_in[0];
    const float* W   = (const float*)d_in[1];
    const float* b   = (const float*)d_in[2];
    const float* emb = (const float*)d_in[3];

    float* out  = (float*)d_out;
    float* outq = out;
    float* outi = out + (size_t)M_ROWS * DIMS;
    float* outl = outi + M_ROWS;

    static int smem_set = 0;
    if (!smem_set) {
        cudaFuncSetAttribute(coarse_kernel, cudaFuncAttributeMaxDynamicSharedMemorySize, SMEM_NEED);
        cudaFuncSetAttribute(gemm_z_tc, cudaFuncAttributeMaxDynamicSharedMemorySize, GSMEM_NEED);
        smem_set = 1;
    }

    conv_w_kernel<<<32, 256>>>(W);
    conv_emb_kernel<<<NCODES / 8, 256>>>(emb);
    gemm_z_tc<<<M_ROWS / 128, 256, GSMEM_NEED>>>(x, W, b);
    coarse_kernel<<<M_ROWS / 128, 256, SMEM_NEED>>>();
    recheck_kernel<<<M_ROWS / 8, 256>>>(emb);
    gather_kernel<<<M_ROWS, 256>>>(emb, outq, outi);
    loss_kernel<<<1, 256>>>(outl);
}

// round 10
// speedup vs baseline: 1.5630x; 1.5630x over previous
#include <cuda_runtime.h>
#include <cuda_bf16.h>
#include <math_constants.h>
#include <cstdint>

#define M_ROWS 32768
#define DIMS   256
#define NCODES 1024
#define NCAND  8
#define MARGIN 2.5e-4f

#if defined(__CUDA_ARCH_FEAT_SM103_ALL) || defined(__CUDA_ARCH_FEAT_SM100_ALL) || defined(__CUDA_ARCH_FEAT_SM101_ALL)
#define HAS_TC 1
#else
#define HAS_TC 0
#endif

// ---------------- device-global scratch ------------------------------------
__device__ float g_z[M_ROWS * DIMS];
__device__ __align__(16) __nv_bfloat16 g_wh[DIMS * DIMS];
__device__ __align__(16) __nv_bfloat16 g_wm[DIMS * DIMS];
__device__ __align__(16) __nv_bfloat16 g_wl[DIMS * DIMS];
__device__ __align__(16) __nv_bfloat16 g_eh[NCODES * DIMS];
__device__ __align__(16) __nv_bfloat16 g_el[NCODES * DIMS];
__device__ float g_cnorm[NCODES];
__device__ float g_rownorm[M_ROWS];
__device__ int   g_idx[M_ROWS];
__device__ float g_rowloss[M_ROWS];
__device__ int   g_cands[M_ROWS * NCAND];
__device__ int   g_ccount[M_ROWS];

// ---------------- PTX helpers ------------------------------------------------
__device__ __forceinline__ uint32_t smem_u32(const void* p) {
    uint32_t a;
    asm("{ .reg .u64 t; cvta.to.shared.u64 t, %1; cvt.u32.u64 %0, t; }" : "=r"(a) : "l"(p));
    return a;
}
#define CP_ASYNC16(s, g) asm volatile("cp.async.cg.shared.global [%0], [%1], 16;" :: "r"(s), "l"(g) : "memory")
#define CP_COMMIT()      asm volatile("cp.async.commit_group;" ::: "memory")
#define CP_WAIT0()       asm volatile("cp.async.wait_group 0;" ::: "memory")
#define FENCE_ASYNC()    asm volatile("fence.proxy.async.shared::cta;" ::: "memory")
#define MBAR_INIT(mb, c) asm volatile("mbarrier.init.shared.b64 [%0], %1;" :: "r"(mb), "r"(c) : "memory")
#define MBAR_INVAL(mb)   asm volatile("mbarrier.inval.shared.b64 [%0];" :: "r"(mb) : "memory")
#define MBAR_WAIT(mb, ph) do {                                                 \
    uint32_t _m = (mb), _p = (ph), _d;                                         \
    asm volatile("{\n\t.reg .pred p;\n\t"                                      \
        "mbarrier.try_wait.parity.acquire.cta.shared::cta.b64 p, [%1], %2;\n\t"\
        "selp.b32 %0, 1, 0, p;\n\t}" : "=r"(_d) : "r"(_m), "r"(_p) : "memory");\
    if (!_d) {                                                                 \
        asm volatile("{\n\t.reg .pred P1;\n\tWL_%=:\n\t"                       \
            "mbarrier.try_wait.parity.acquire.cta.shared::cta.b64 P1, [%0], %1, 0x989680;\n\t" \
            "@P1 bra.uni WD_%=;\n\tbra.uni WL_%=;\n\tWD_%=:\n\t}"              \
            :: "r"(_m), "r"(_p) : "memory");                                   \
    }                                                                          \
} while (0)

#if HAS_TC
__device__ __forceinline__ uint32_t elect_one() {
    uint32_t p;
    asm volatile("{\n\t.reg .pred p;\n\telect.sync _|p, 0xFFFFFFFF;\n\t"
                 "selp.b32 %0, 1, 0, p;\n\t}" : "=r"(p));
    return p;
}
#define TC_ALLOC(sa, n)  asm volatile("tcgen05.alloc.cta_group::1.sync.aligned.shared::cta.b32 [%0], %1;" :: "r"(sa), "r"(n) : "memory")
#define TC_RELINQ()      asm volatile("tcgen05.relinquish_alloc_permit.cta_group::1.sync.aligned;")
#define TC_DEALLOC(t, n) asm volatile("tcgen05.dealloc.cta_group::1.sync.aligned.b32 %0, %1;" :: "r"(t), "r"(n))
#define TC_COMMIT(mb)    asm volatile("tcgen05.commit.cta_group::1.mbarrier::arrive::one.shared::cluster.b64 [%0];" :: "r"(mb) : "memory")
#define TC_WAIT_LD()     asm volatile("tcgen05.wait::ld.sync.aligned;" ::: "memory")
#define TC_WAIT_ST()     asm volatile("tcgen05.wait::st.sync.aligned;" ::: "memory")
#define TC_FENCE_B()     asm volatile("tcgen05.fence::before_thread_sync;" ::: "memory")
#define TC_FENCE_A()     asm volatile("tcgen05.fence::after_thread_sync;" ::: "memory")

static constexpr uint64_t DESC_SW128 =
    (uint64_t(2) << 61) | (uint64_t(1) << 46) | (uint64_t(64) << 32) | (uint64_t(1) << 16);
__device__ __forceinline__ uint64_t make_desc(uint32_t a) {
    return DESC_SW128 | ((uint64_t)(a >> 4) & 0x3FFF);
}
__device__ __forceinline__ void mma_f16_ts(uint32_t d, uint32_t a, uint64_t b,
                                           uint32_t idesc, bool en) {
    uint32_t e = en ? 1u : 0u, z = 0u;
    asm volatile("{\n\t.reg .pred p;\n\tsetp.ne.u32 p, %5, 0;\n\t"
        "tcgen05.mma.cta_group::1.kind::f16 [%0], [%1], %2, %3, {%4, %4, %4, %4}, p;\n\t}"
        :: "r"(d), "r"(a), "l"(b), "r"(idesc), "r"(z), "r"(e) : "memory");
}
__device__ __forceinline__ void mma_f16_ss(uint32_t d, uint64_t a, uint64_t b,
                                           uint32_t idesc, bool en) {
    uint32_t e = en ? 1u : 0u, z = 0u;
    asm volatile("{\n\t.reg .pred p;\n\tsetp.ne.u32 p, %5, 0;\n\t"
        "tcgen05.mma.cta_group::1.kind::f16 [%0], %1, %2, %3, {%4, %4, %4, %4}, p;\n\t}"
        :: "r"(d), "l"(a), "l"(b), "r"(idesc), "r"(z), "r"(e) : "memory");
}
__device__ __forceinline__ void ldtm32(uint32_t* r, uint32_t a) {
    asm volatile("tcgen05.ld.sync.aligned.32x32b.x32.b32 "
        "{%0,%1,%2,%3,%4,%5,%6,%7,%8,%9,%10,%11,%12,%13,%14,%15,"
        "%16,%17,%18,%19,%20,%21,%22,%23,%24,%25,%26,%27,%28,%29,%30,%31}, [%32];"
        : "=r"(r[0]),"=r"(r[1]),"=r"(r[2]),"=r"(r[3]),"=r"(r[4]),"=r"(r[5]),
          "=r"(r[6]),"=r"(r[7]),"=r"(r[8]),"=r"(r[9]),"=r"(r[10]),"=r"(r[11]),
          "=r"(r[12]),"=r"(r[13]),"=r"(r[14]),"=r"(r[15]),"=r"(r[16]),"=r"(r[17]),
          "=r"(r[18]),"=r"(r[19]),"=r"(r[20]),"=r"(r[21]),"=r"(r[22]),"=r"(r[23]),
          "=r"(r[24]),"=r"(r[25]),"=r"(r[26]),"=r"(r[27]),"=r"(r[28]),"=r"(r[29]),
          "=r"(r[30]),"=r"(r[31]) : "r"(a));
}
__device__ __forceinline__ void sttm32(uint32_t a, const uint32_t* r) {
    asm volatile("tcgen05.st.sync.aligned.32x32b.x32.b32 [%0], "
        "{%1,%2,%3,%4,%5,%6,%7,%8,%9,%10,%11,%12,%13,%14,%15,%16,"
        "%17,%18,%19,%20,%21,%22,%23,%24,%25,%26,%27,%28,%29,%30,%31,%32};"
        :: "r"(a),
           "r"(r[0]),"r"(r[1]),"r"(r[2]),"r"(r[3]),"r"(r[4]),"r"(r[5]),
           "r"(r[6]),"r"(r[7]),"r"(r[8]),"r"(r[9]),"r"(r[10]),"r"(r[11]),
           "r"(r[12]),"r"(r[13]),"r"(r[14]),"r"(r[15]),"r"(r[16]),"r"(r[17]),
           "r"(r[18]),"r"(r[19]),"r"(r[20]),"r"(r[21]),"r"(r[22]),"r"(r[23]),
           "r"(r[24]),"r"(r[25]),"r"(r[26]),"r"(r[27]),"r"(r[28]),"r"(r[29]),
           "r"(r[30]),"r"(r[31]) : "memory");
}
static constexpr uint32_t MMA_IDESC =   // coarse: N=64
    (1u << 4) | (1u << 7) | (1u << 10) | (8u << 17) | (8u << 24);
static constexpr uint32_t IDESC_G =     // gemm: N=256
    (1u << 4) | (1u << 7) | (1u << 10) | (32u << 17) | (8u << 24);
#endif // HAS_TC

__device__ __forceinline__ void split3(float a, __nv_bfloat16& h, __nv_bfloat16& m,
                                       __nv_bfloat16& l) {
    h = __float2bfloat16(a);
    float r = a - __bfloat162float(h);
    m = __float2bfloat16(r);
    l = __float2bfloat16(r - __bfloat162float(m));
}
__device__ __forceinline__ uint32_t toff(int r, int k) {
    uint32_t lin = (uint32_t)(r >> 3) * 1024u + (uint32_t)(k >> 6) * 8192u
                 + (uint32_t)(r & 7) * 128u + (uint32_t)(k & 63) * 2u;
    return lin ^ ((lin >> 3) & 0x70u);
}
// top-4 tracker: m1<=m2<=m3<=m4, indices for first three (first-index on ties)
__device__ __forceinline__ void top4_upd(float d, int col,
                                         float& m1, int& i1, float& m2, int& i2,
                                         float& m3, int& i3, float& m4) {
    if (d < m1)      { m4 = m3; m3 = m2; i3 = i2; m2 = m1; i2 = i1; m1 = d; i1 = col; }
    else if (d < m2) { m4 = m3; m3 = m2; i3 = i2; m2 = d; i2 = col; }
    else if (d < m3) { m4 = m3; m3 = d; i3 = col; }
    else if (d < m4) { m4 = d; }
}

// ---------------- K0: W -> 3-way bf16 split ---------------------------------
__global__ void conv_w_kernel(const float* __restrict__ W)
{
    size_t base = ((size_t)blockIdx.x * 256 + threadIdx.x) * 8;
    float v[8];
    *reinterpret_cast<float4*>(v)     = *reinterpret_cast<const float4*>(W + base);
    *reinterpret_cast<float4*>(v + 4) = *reinterpret_cast<const float4*>(W + base + 4);
    __nv_bfloat16 h[8], m[8], l[8];
#pragma unroll
    for (int j = 0; j < 8; j++) split3(v[j], h[j], m[j], l[j]);
    *reinterpret_cast<uint4*>(&g_wh[base]) = *reinterpret_cast<uint4*>(h);
    *reinterpret_cast<uint4*>(&g_wm[base]) = *reinterpret_cast<uint4*>(m);
    *reinterpret_cast<uint4*>(&g_wl[base]) = *reinterpret_cast<uint4*>(l);
}

// ---------------- K1: z = x @ W^T + b  (tcgen05, 3-split bf16) ---------------
static constexpr uint32_t G_A = 0;
static constexpr uint32_t G_B = 98304;
static constexpr uint32_t G_BIAS = 196608;
static constexpr uint32_t G_MB = 197632, G_TP = 197640;
static constexpr uint32_t GSMEM_NEED = 197644 + 1040;

__global__ __launch_bounds__(256, 1)
void gemm_z_tc(const float* __restrict__ x, const float* __restrict__ W,
               const float* __restrict__ bias)
{
#if HAS_TC
    extern __shared__ char smraw[];
    uint32_t raw = smem_u32(smraw);
    uint32_t sb  = (raw + 1023u) & ~1023u;
    char* sm = smraw + (sb - raw);
    float* sbias = reinterpret_cast<float*>(sm + G_BIAS);

    const int tid = threadIdx.x;
    const int rb  = blockIdx.x * 128;

    if (tid < 32) TC_ALLOC(sb + G_TP, 256);
    if (tid == 0) MBAR_INIT(sb + G_MB, 1);
    sbias[tid] = bias[tid];
    __syncthreads();
    uint32_t tmem;
    asm volatile("ld.shared.b32 %0, [%1];" : "=r"(tmem) : "r"(sb + G_TP));

#pragma unroll
    for (int g = tid; g < 1024; g += 256) {
        int r = g >> 3, k8 = (g & 7) << 3;
        const float* src = x + (size_t)(rb + r) * DIMS + k8;
        float v[8];
        *reinterpret_cast<float4*>(v)     = *reinterpret_cast<const float4*>(src);
        *reinterpret_cast<float4*>(v + 4) = *reinterpret_cast<const float4*>(src + 4);
        __nv_bfloat16 h[8], m[8], l[8];
#pragma unroll
        for (int j = 0; j < 8; j++) split3(v[j], h[j], m[j], l[j]);
        uint32_t o = toff(r, k8);
        *reinterpret_cast<uint4*>(sm + G_A + o)         = *reinterpret_cast<uint4*>(h);
        *reinterpret_cast<uint4*>(sm + G_A + 16384 + o) = *reinterpret_cast<uint4*>(m);
        *reinterpret_cast<uint4*>(sm + G_A + 32768 + o) = *reinterpret_cast<uint4*>(l);
    }
    FENCE_ASYNC();

    for (int ch = 0; ch < 4; ++ch) {
        for (int c = tid; c < 6144; c += 256) {
            int s = c >> 11, ci = c & 2047;
            int r = ci >> 3, k8 = (ci & 7) << 3;
            const __nv_bfloat16* src =
                (s == 0 ? g_wh : s == 1 ? g_wm : g_wl) + (size_t)r * DIMS + ch * 64 + k8;
            CP_ASYNC16(sb + G_B + (uint32_t)s * 32768u + toff(r, k8), src);
        }
        CP_COMMIT(); CP_WAIT0();
        __syncthreads();

        if (tid < 32 && elect_one()) {
            TC_FENCE_A();
            uint64_t A0 = make_desc(sb + G_A + (uint32_t)(ch & 1) * 49152u);
            uint64_t A1 = A0 + 1024, A2 = A0 + 2048;
            uint64_t B0 = make_desc(sb + G_B);
            uint64_t B1 = B0 + 2048, B2 = B0 + 4096;
#pragma unroll
            for (int kk = 0; kk < 4; ++kk) {
                uint64_t off = (uint64_t)(kk * 2);
                mma_f16_ss(tmem, A0 + off, B0 + off, IDESC_G, !(ch == 0 && kk == 0));
                mma_f16_ss(tmem, A0 + off, B1 + off, IDESC_G, true);
                mma_f16_ss(tmem, A1 + off, B0 + off, IDESC_G, true);
                mma_f16_ss(tmem, A1 + off, B1 + off, IDESC_G, true);
                mma_f16_ss(tmem, A0 + off, B2 + off, IDESC_G, true);
                mma_f16_ss(tmem, A2 + off, B0 + off, IDESC_G, true);
            }
            TC_COMMIT(sb + G_MB);
        }
        if (ch < 3) {
            uint32_t abase = G_A + (uint32_t)((ch + 1) & 1) * 49152u;
#pragma unroll
            for (int g = tid; g < 1024; g += 256) {
                int r = g >> 3, k8 = (g & 7) << 3;
                const float* src = x + (size_t)(rb + r) * DIMS + (ch + 1) * 64 + k8;
                float v[8];
                *reinterpret_cast<float4*>(v)     = *reinterpret_cast<const float4*>(src);
                *reinterpret_cast<float4*>(v + 4) = *reinterpret_cast<const float4*>(src + 4);
                __nv_bfloat16 h[8], m[8], l[8];
#pragma unroll
                for (int j = 0; j < 8; j++) split3(v[j], h[j], m[j], l[j]);
                uint32_t o = toff(r, k8);
                *reinterpret_cast<uint4*>(sm + abase + o)         = *reinterpret_cast<uint4*>(h);
                *reinterpret_cast<uint4*>(sm + abase + 16384 + o) = *reinterpret_cast<uint4*>(m);
                *reinterpret_cast<uint4*>(sm + abase + 32768 + o) = *reinterpret_cast<uint4*>(l);
            }
            FENCE_ASYNC();
        }
        MBAR_WAIT(sb + G_MB, ch & 1);
        __syncthreads();
    }
    TC_FENCE_A();

    const int sub = (tid >> 5) & 3, half = tid >> 7, lane = tid & 31;
    const int row = rb + sub * 32 + lane;
    const uint32_t woff = ((uint32_t)sub) << 21;
#pragma unroll
    for (int q = 0; q < 4; ++q) {
        uint32_t regs[32];
        ldtm32(regs, tmem + half * 128 + q * 32 + woff);
        TC_WAIT_LD();
        int c0 = half * 128 + q * 32;
#pragma unroll
        for (int j = 0; j < 32; j += 4) {
            float4 v;
            v.x = __uint_as_float(regs[j+0]) + sbias[c0+j+0];
            v.y = __uint_as_float(regs[j+1]) + sbias[c0+j+1];
            v.z = __uint_as_float(regs[j+2]) + sbias[c0+j+2];
            v.w = __uint_as_float(regs[j+3]) + sbias[c0+j+3];
            *reinterpret_cast<float4*>(&g_z[(size_t)row * DIMS + c0 + j]) = v;
        }
    }
    TC_FENCE_B();
    __syncthreads();
    if (tid == 0) MBAR_INVAL(sb + G_MB);
    __syncthreads();
    if (tid < 32) { TC_RELINQ(); TC_DEALLOC(tmem, 256); }
#else
    int tid = threadIdx.x, rb = blockIdx.x * 128;
    for (int o = tid; o < 128 * DIMS; o += 256) {
        int r = rb + (o >> 8), c = o & 255;
        float acc = 0.f;
        for (int k = 0; k < DIMS; k++)
            acc += x[(size_t)r * DIMS + k] * W[(size_t)c * DIMS + k];
        g_z[(size_t)r * DIMS + c] = acc + bias[c];
    }
#endif
}

// ---------------- K2: emb -> split bf16 + code norms -------------------------
__global__ void conv_emb_kernel(const float* __restrict__ emb)
{
    int row = blockIdx.x * 8 + (threadIdx.x >> 5);
    int lane = threadIdx.x & 31;
    const float* p = &emb[(size_t)row * DIMS + lane * 8];
    float v[8];
    *reinterpret_cast<float4*>(v)     = *reinterpret_cast<const float4*>(p);
    *reinterpret_cast<float4*>(v + 4) = *reinterpret_cast<const float4*>(p + 4);
    uint4 oh, ol;
    uint32_t* ohp = reinterpret_cast<uint32_t*>(&oh);
    uint32_t* olp = reinterpret_cast<uint32_t*>(&ol);
    float s = 0.f;
#pragma unroll
    for (int j = 0; j < 4; j++) {
        float a0 = v[2*j], a1 = v[2*j+1];
        __nv_bfloat16 h0 = __float2bfloat16(a0), h1 = __float2bfloat16(a1);
        float r0 = a0 - __bfloat162float(h0), r1 = a1 - __bfloat162float(h1);
        __nv_bfloat162 hp; hp.x = h0; hp.y = h1;
        __nv_bfloat162 lp = __floats2bfloat162_rn(r0, r1);
        ohp[j] = *reinterpret_cast<uint32_t*>(&hp);
        olp[j] = *reinterpret_cast<uint32_t*>(&lp);
        s += a0*a0 + a1*a1;
    }
    *reinterpret_cast<uint4*>(&g_eh[(size_t)row * DIMS + lane * 8]) = oh;
    *reinterpret_cast<uint4*>(&g_el[(size_t)row * DIMS + lane * 8]) = ol;
#pragma unroll
    for (int ofs = 16; ofs > 0; ofs >>= 1) s += __shfl_down_sync(0xffffffffu, s, ofs);
    if (lane == 0) g_cnorm[row] = s;
}

// ---------------- K3: split-bf16 tcgen05 coarse argmin (top-4 epilogue) ------
static constexpr uint32_t S_B = 0, S_CN = 131072, S_MB = 135168, S_TP = 135184;
static constexpr uint32_t SMEM_NEED = 135188 + 1024 + 12;

#if HAS_TC
__device__ __forceinline__ void load_btile_async(uint32_t sbase, int tile,
                                                 int t, int nth)
{
    const __nv_bfloat16* eh = g_eh + (size_t)tile * 64 * DIMS;
    const __nv_bfloat16* el = g_el + (size_t)tile * 64 * DIMS;
    for (int c = t; c < 4096; c += nth) {
        int part = c >> 11;
        int ci = c & 2047;
        int r = ci >> 5, k = (ci & 31) << 3;
        const __nv_bfloat16* src = (part ? el : eh) + r * DIMS + k;
        CP_ASYNC16(sbase + (uint32_t)part * 32768u + toff(r, k), src);
    }
}
#endif

__global__ __launch_bounds__(256, 1)
void coarse_kernel()
{
#if HAS_TC
    extern __shared__ char smraw[];
    uint32_t raw = smem_u32(smraw);
    uint32_t sb  = (raw + 1023u) & ~1023u;
    char* sm = smraw + (sb - raw);
    float* scn = reinterpret_cast<float*>(sm + S_CN);

    const int tid = threadIdx.x;
    const int w = tid >> 5, lane = tid & 31;
    const int sub = w & 3, half = w >> 2;
    const int rb = blockIdx.x * 128;
    const int myrow = sub * 32 + lane;
    const int rowg = rb + myrow;
    const uint32_t woff = ((uint32_t)sub) << 21;

    if (w == 0) TC_ALLOC(sb + S_TP, 512);
    if (tid == 0) { MBAR_INIT(sb + S_MB, 1); MBAR_INIT(sb + S_MB + 8, 1); }
#pragma unroll
    for (int i = tid; i < NCODES; i += 256) scn[i] = g_cnorm[i];
    __syncthreads();
    uint32_t tmem;
    asm volatile("ld.shared.b32 %0, [%1];" : "=r"(tmem) : "r"(sb + S_TP));

    float rn = 0.f;
    if (half == 0) {
        const float* zp = &g_z[(size_t)rowg * DIMS];
#pragma unroll
        for (int ch = 0; ch < 4; ++ch) {
            float v[64];
#pragma unroll
            for (int q = 0; q < 16; ++q)
                *reinterpret_cast<float4*>(v + q * 4) =
                    *reinterpret_cast<const float4*>(zp + ch * 64 + q * 4);
            uint32_t hi[32], lo[32];
#pragma unroll
            for (int j = 0; j < 32; ++j) {
                float a0 = v[2*j], a1 = v[2*j+1];
                rn += a0*a0 + a1*a1;
                __nv_bfloat16 h0 = __float2bfloat16(a0), h1 = __float2bfloat16(a1);
                float r0 = a0 - __bfloat162float(h0), r1 = a1 - __bfloat162float(h1);
                __nv_bfloat162 hp; hp.x = h0; hp.y = h1;
                __nv_bfloat162 lp = __floats2bfloat162_rn(r0, r1);
                hi[j] = *reinterpret_cast<uint32_t*>(&hp);
                lo[j] = *reinterpret_cast<uint32_t*>(&lp);
            }
            sttm32(tmem +       ch * 32 + woff, hi);
            sttm32(tmem + 128 + ch * 32 + woff, lo);
        }
        TC_WAIT_ST();
        TC_FENCE_B();
        g_rownorm[rowg] = rn;
    } else {
        load_btile_async(sb + S_B, 0, tid - 128, 128);
        CP_COMMIT();
    }
    __syncthreads();
    if (half == 1) rn = g_rownorm[rowg];

    float m1 = CUDART_INF_F, m2 = CUDART_INF_F, m3 = CUDART_INF_F, m4 = CUDART_INF_F;
    int i1 = 0, i2 = 0, i3 = 0;

    for (int i = 0; i < 16; ++i) {
        const int buf = i & 1;
        CP_WAIT0();
        __syncthreads();
        if (w == 0 && elect_one()) {
            TC_FENCE_A();
            uint64_t bh = make_desc(sb + S_B + (uint32_t)buf * 65536u);
            uint64_t bl = bh + 2048;
            uint32_t D  = tmem + 256 + buf * 64;
#pragma unroll
            for (int c = 0; c < 16; ++c) {
                uint64_t off = (uint64_t)((c >> 2) * 512 + (c & 3) * 2);
                uint32_t ah = tmem + c * 8, al = tmem + 128 + c * 8;
                mma_f16_ts(D, ah, bh + off, MMA_IDESC, c > 0);
                mma_f16_ts(D, ah, bl + off, MMA_IDESC, true);
                mma_f16_ts(D, al, bh + off, MMA_IDESC, true);
            }
            TC_COMMIT(sb + S_MB + 8 * buf);
        }
        if (i >= 1) { MBAR_WAIT(sb + S_MB + 8 * (buf ^ 1), ((i - 1) >> 1) & 1); TC_FENCE_A(); }
        if (i < 15) { load_btile_async(sb + S_B + (uint32_t)(buf ^ 1) * 65536u, i + 1, tid, 256); CP_COMMIT(); }
        if (i >= 1) {
            uint32_t regs[32];
            ldtm32(regs, tmem + 256 + (buf ^ 1) * 64 + (half << 5) + woff);
            TC_WAIT_LD();
            const int col0 = (i - 1) * 64 + (half << 5);
#pragma unroll
            for (int r = 0; r < 32; ++r) {
                int col = col0 + r;
                float d = __fadd_rn(rn, scn[col]) - 2.0f * __uint_as_float(regs[r]);
                top4_upd(d, col, m1, i1, m2, i2, m3, i3, m4);
            }
            TC_FENCE_B();
        }
    }
    MBAR_WAIT(sb + S_MB + 8, 1);
    TC_FENCE_A();
    {
        uint32_t regs[32];
        ldtm32(regs, tmem + 256 + 64 + (half << 5) + woff);
        TC_WAIT_LD();
        const int col0 = 15 * 64 + (half << 5);
#pragma unroll
        for (int r = 0; r < 32; ++r) {
            int col = col0 + r;
            float d = __fadd_rn(rn, scn[col]) - 2.0f * __uint_as_float(regs[r]);
            top4_upd(d, col, m1, i1, m2, i2, m3, i3, m4);
        }
    }
    TC_FENCE_B();

    // ---- merge halves: each half writes (m1,i1,m2,i2,m3,i3,m4) -> 8 slots ---
    {
        float* blk = reinterpret_cast<float*>(sm + S_B) + (myrow * 2 + half) * 8;
        blk[0] = m1;
        reinterpret_cast<int*>(blk)[1] = i1;
        blk[2] = m2;
        reinterpret_cast<int*>(blk)[3] = i2;
        blk[4] = m3;
        reinterpret_cast<int*>(blk)[5] = i3;
        blk[6] = m4;
    }
    __syncthreads();
    if (half == 0) {
        float* A = reinterpret_cast<float*>(sm + S_B) + (myrow * 2) * 8;
        float* B = A + 8;
        float av[4] = { A[0], A[2], A[4], A[6] };
        int   ai[4] = { reinterpret_cast<int*>(A)[1], reinterpret_cast<int*>(A)[3],
                        reinterpret_cast<int*>(A)[5], 0x7fffffff };
        float bv[4] = { B[0], B[2], B[4], B[6] };
        int   bi[4] = { reinterpret_cast<int*>(B)[1], reinterpret_cast<int*>(B)[3],
                        reinterpret_cast<int*>(B)[5], 0x7fffffff };
        float gm[4]; int gi[4];
        int pa = 0, pb = 0;
#pragma unroll
        for (int t = 0; t < 4; ++t) {
            bool takeB = (bv[pb] < av[pa]) || (bv[pb] == av[pa] && bi[pb] < ai[pa]);
            if (takeB) { gm[t] = bv[pb]; gi[t] = bi[pb]; pb++; }
            else       { gm[t] = av[pa]; gi[t] = ai[pa]; pa++; }
        }
        g_idx[rowg] = gi[0];
        float thr = gm[0] + MARGIN;
        if (gm[1] > thr) {
            g_ccount[rowg] = 0;                 // decided
        } else if (gm[2] > thr) {
            g_cands[(size_t)rowg * NCAND + 0] = gi[0];
            g_cands[(size_t)rowg * NCAND + 1] = gi[1];
            g_ccount[rowg] = 2;
        } else if (gm[3] > thr) {
            g_cands[(size_t)rowg * NCAND + 0] = gi[0];
            g_cands[(size_t)rowg * NCAND + 1] = gi[1];
            g_cands[(size_t)rowg * NCAND + 2] = gi[2];
            g_ccount[rowg] = 3;
        } else {
            g_ccount[rowg] = -1;                // rare: fast block full scan
        }
    }
    __syncthreads();
    if (tid == 0) { MBAR_INVAL(sb + S_MB); MBAR_INVAL(sb + S_MB + 8); }
    __syncthreads();
    if (w == 0) { TC_RELINQ(); TC_DEALLOC(tmem, 512); }
#else
    int r = blockIdx.x * 128 + (int)threadIdx.x;
    if (threadIdx.x < 128) {
        float s = 0.f;
        for (int i = 0; i < DIMS; i++) { float v = g_z[(size_t)r * DIMS + i]; s += v * v; }
        g_rownorm[r] = s;
        g_idx[r] = 0;
        g_ccount[r] = -1;
    }
#endif
}

// ---------------- K4a: exact fp32 recheck of 2-3 candidates ------------------
__global__ __launch_bounds__(256)
void recheck_kernel(const float* __restrict__ emb)
{
    int row  = blockIdx.x * 8 + (threadIdx.x >> 5);
    int lane = threadIdx.x & 31;
    int cnt  = g_ccount[row];
    if (cnt <= 0) return;   // 0 = decided, -1 = handled by recheck_full

    const float* zp = &g_z[(size_t)row * DIMS];
    float zv[8];
#pragma unroll
    for (int i = 0; i < 8; i++) zv[i] = zp[lane + 32 * i];
    float rn = g_rownorm[row];

    float bv = CUDART_INF_F;
    int   bi = 0x7fffffff;
    for (int c = 0; c < cnt; c++) {
        int idx = g_cands[(size_t)row * NCAND + c];
        const float* ep = &emb[(size_t)idx * DIMS];
        float dot = 0.f;
#pragma unroll
        for (int i = 0; i < 8; i++) dot += zv[i] * ep[lane + 32 * i];
#pragma unroll
        for (int o = 16; o > 0; o >>= 1) dot += __shfl_down_sync(0xffffffffu, dot, o);
        if (lane == 0) {
            float t = __fadd_rn(rn, g_cnorm[idx]);
            float dist = __fadd_rn(t, -__fmul_rn(2.0f, dot));
            if (dist < bv || (dist == bv && idx < bi)) { bv = dist; bi = idx; }
        }
    }
    if (lane == 0) g_idx[row] = bi;
}

// ---------------- K4b: fast exact full scan for overflow rows ----------------
__global__ __launch_bounds__(256)
void recheck_full_kernel(const float* __restrict__ emb)
{
    int row = blockIdx.x;
    if (g_ccount[row] != -1) return;

    __shared__ float sz[DIMS];
    __shared__ float sv[256];
    __shared__ int   si[256];
    int t = threadIdx.x;
    sz[t] = g_z[(size_t)row * DIMS + t];
    float rn = g_rownorm[row];
    __syncthreads();

    float best = CUDART_INF_F;
    int   bi = 0x7fffffff;
#pragma unroll
    for (int q = 0; q < 4; q++) {
        int c = q * 256 + t;
        const float* ep = &emb[(size_t)c * DIMS];
        float d0 = 0.f, d1 = 0.f, d2 = 0.f, d3 = 0.f;
#pragma unroll 8
        for (int i = 0; i < DIMS; i += 4) {
            d0 += sz[i+0] * ep[i+0];
            d1 += sz[i+1] * ep[i+1];
            d2 += sz[i+2] * ep[i+2];
            d3 += sz[i+3] * ep[i+3];
        }
        float dot = (d0 + d1) + (d2 + d3);
        float dist = __fadd_rn(__fadd_rn(rn, g_cnorm[c]), -__fmul_rn(2.0f, dot));
        if (dist < best || (dist == best && c < bi)) { best = dist; bi = c; }
    }
    sv[t] = best; si[t] = bi;
    __syncthreads();
    for (int o = 128; o > 0; o >>= 1) {
        if (t < o) {
            if (sv[t+o] < sv[t] || (sv[t+o] == sv[t] && si[t+o] < si[t])) {
                sv[t] = sv[t+o]; si[t] = si[t+o];
            }
        }
        __syncthreads();
    }
    if (t == 0) g_idx[row] = si[0];
}

// ---------------- K5: gather + per-row loss -----------------------------------
__global__ void gather_kernel(const float* __restrict__ emb,
                              float* __restrict__ outq, float* __restrict__ outi)
{
    __shared__ float ws[8];
    int row = blockIdx.x, d = threadIdx.x;
    int idx = g_idx[row];
    float e = emb[(size_t)idx * DIMS + d];
    float z = g_z[(size_t)row * DIMS + d];
    outq[(size_t)row * DIMS + d] = e;
    float diff = e - z;
    float s = diff * diff;
#pragma unroll
    for (int o = 16; o > 0; o >>= 1) s += __shfl_down_sync(0xffffffffu, s, o);
    int lane = d & 31, w = d >> 5;
    if (lane == 0) ws[w] = s;
    __syncthreads();
    if (d == 0) {
        float tot = 0.f;
#pragma unroll
        for (int i = 0; i < 8; i++) tot += ws[i];
        g_rowloss[row] = tot;
        outi[row] = (float)idx;
    }
}

// ---------------- K6: loss reduction ------------------------------------------
__global__ void loss_kernel(float* __restrict__ outl)
{
    __shared__ double sd[256];
    double s = 0.0;
    for (int i = threadIdx.x; i < M_ROWS; i += 256) s += (double)g_rowloss[i];
    sd[threadIdx.x] = s;
    __syncthreads();
    for (int o = 128; o > 0; o >>= 1) {
        if (threadIdx.x < o) sd[threadIdx.x] += sd[threadIdx.x + o];
        __syncthreads();
    }
    if (threadIdx.x == 0) outl[0] = (float)(1.25 * sd[0] / 8388608.0);
}

// ---------------- launch --------------------------------------------------------
extern "C" void kernel_launch(void* const* d_in, const int* in_sizes, int n_in,
                              void* d_out, int out_size)
{
    const float* x   = (const float*)d_in[0];
    const float* W   = (const float*)d_in[1];
    const float* b   = (const float*)d_in[2];
    const float* emb = (const float*)d_in[3];

    float* out  = (float*)d_out;
    float* outq = out;
    float* outi = out + (size_t)M_ROWS * DIMS;
    float* outl = outi + M_ROWS;

    static int smem_set = 0;
    if (!smem_set) {
        cudaFuncSetAttribute(coarse_kernel, cudaFuncAttributeMaxDynamicSharedMemorySize, SMEM_NEED);
        cudaFuncSetAttribute(gemm_z_tc, cudaFuncAttributeMaxDynamicSharedMemorySize, GSMEM_NEED);
        smem_set = 1;
    }

    conv_w_kernel<<<32, 256>>>(W);
    conv_emb_kernel<<<NCODES / 8, 256>>>(emb);
    gemm_z_tc<<<M_ROWS / 128, 256, GSMEM_NEED>>>(x, W, b);
    coarse_kernel<<<M_ROWS / 128, 256, SMEM_NEED>>>();
    recheck_kernel<<<M_ROWS / 8, 256>>>(emb);
    recheck_full_kernel<<<M_ROWS, 256>>>(emb);
    gather_kernel<<<M_ROWS, 256>>>(emb, outq, outi);
    loss_kernel<<<1, 256>>>(outl);
}

// round 11
// speedup vs baseline: 2.7205x; 1.7405x over previous
#include <cuda_runtime.h>
#include <cuda_bf16.h>
#include <math_constants.h>
#include <cstdint>

#define M_ROWS 32768
#define DIMS   256
#define NCODES 1024
#define NC_H   24            // candidate slots per half
#define CSTRIDE 48           // per-row stride in g_cands
#define MARGIN 2.5e-4f

#if defined(__CUDA_ARCH_FEAT_SM103_ALL) || defined(__CUDA_ARCH_FEAT_SM100_ALL) || defined(__CUDA_ARCH_FEAT_SM101_ALL)
#define HAS_TC 1
#else
#define HAS_TC 0
#endif

// ---------------- device-global scratch ------------------------------------
__device__ float g_z[M_ROWS * DIMS];
__device__ __align__(16) __nv_bfloat16 g_wh[DIMS * DIMS];
__device__ __align__(16) __nv_bfloat16 g_wm[DIMS * DIMS];
__device__ __align__(16) __nv_bfloat16 g_wl[DIMS * DIMS];
__device__ __align__(16) __nv_bfloat16 g_eh[NCODES * DIMS];
__device__ __align__(16) __nv_bfloat16 g_el[NCODES * DIMS];
__device__ float g_cnorm[NCODES];
__device__ float g_rownorm[M_ROWS];
__device__ int   g_idx[M_ROWS];
__device__ float g_rowloss[M_ROWS];
__device__ int   g_cands[(size_t)M_ROWS * CSTRIDE];
__device__ int   g_ccount[M_ROWS];

// ---------------- PTX helpers ------------------------------------------------
__device__ __forceinline__ uint32_t smem_u32(const void* p) {
    uint32_t a;
    asm("{ .reg .u64 t; cvta.to.shared.u64 t, %1; cvt.u32.u64 %0, t; }" : "=r"(a) : "l"(p));
    return a;
}
#define CP_ASYNC16(s, g) asm volatile("cp.async.cg.shared.global [%0], [%1], 16;" :: "r"(s), "l"(g) : "memory")
#define CP_COMMIT()      asm volatile("cp.async.commit_group;" ::: "memory")
#define CP_WAIT0()       asm volatile("cp.async.wait_group 0;" ::: "memory")
#define FENCE_ASYNC()    asm volatile("fence.proxy.async.shared::cta;" ::: "memory")
#define MBAR_INIT(mb, c) asm volatile("mbarrier.init.shared.b64 [%0], %1;" :: "r"(mb), "r"(c) : "memory")
#define MBAR_INVAL(mb)   asm volatile("mbarrier.inval.shared.b64 [%0];" :: "r"(mb) : "memory")
#define MBAR_WAIT(mb, ph) do {                                                 \
    uint32_t _m = (mb), _p = (ph), _d;                                         \
    asm volatile("{\n\t.reg .pred p;\n\t"                                      \
        "mbarrier.try_wait.parity.acquire.cta.shared::cta.b64 p, [%1], %2;\n\t"\
        "selp.b32 %0, 1, 0, p;\n\t}" : "=r"(_d) : "r"(_m), "r"(_p) : "memory");\
    if (!_d) {                                                                 \
        asm volatile("{\n\t.reg .pred P1;\n\tWL_%=:\n\t"                       \
            "mbarrier.try_wait.parity.acquire.cta.shared::cta.b64 P1, [%0], %1, 0x989680;\n\t" \
            "@P1 bra.uni WD_%=;\n\tbra.uni WL_%=;\n\tWD_%=:\n\t}"              \
            :: "r"(_m), "r"(_p) : "memory");                                   \
    }                                                                          \
} while (0)

#if HAS_TC
__device__ __forceinline__ uint32_t elect_one() {
    uint32_t p;
    asm volatile("{\n\t.reg .pred p;\n\telect.sync _|p, 0xFFFFFFFF;\n\t"
                 "selp.b32 %0, 1, 0, p;\n\t}" : "=r"(p));
    return p;
}
#define TC_ALLOC(sa, n)  asm volatile("tcgen05.alloc.cta_group::1.sync.aligned.shared::cta.b32 [%0], %1;" :: "r"(sa), "r"(n) : "memory")
#define TC_RELINQ()      asm volatile("tcgen05.relinquish_alloc_permit.cta_group::1.sync.aligned;")
#define TC_DEALLOC(t, n) asm volatile("tcgen05.dealloc.cta_group::1.sync.aligned.b32 %0, %1;" :: "r"(t), "r"(n))
#define TC_COMMIT(mb)    asm volatile("tcgen05.commit.cta_group::1.mbarrier::arrive::one.shared::cluster.b64 [%0];" :: "r"(mb) : "memory")
#define TC_WAIT_LD()     asm volatile("tcgen05.wait::ld.sync.aligned;" ::: "memory")
#define TC_WAIT_ST()     asm volatile("tcgen05.wait::st.sync.aligned;" ::: "memory")
#define TC_FENCE_B()     asm volatile("tcgen05.fence::before_thread_sync;" ::: "memory")
#define TC_FENCE_A()     asm volatile("tcgen05.fence::after_thread_sync;" ::: "memory")

static constexpr uint64_t DESC_SW128 =
    (uint64_t(2) << 61) | (uint64_t(1) << 46) | (uint64_t(64) << 32) | (uint64_t(1) << 16);
__device__ __forceinline__ uint64_t make_desc(uint32_t a) {
    return DESC_SW128 | ((uint64_t)(a >> 4) & 0x3FFF);
}
__device__ __forceinline__ void mma_f16_ts(uint32_t d, uint32_t a, uint64_t b,
                                           uint32_t idesc, bool en) {
    uint32_t e = en ? 1u : 0u, z = 0u;
    asm volatile("{\n\t.reg .pred p;\n\tsetp.ne.u32 p, %5, 0;\n\t"
        "tcgen05.mma.cta_group::1.kind::f16 [%0], [%1], %2, %3, {%4, %4, %4, %4}, p;\n\t}"
        :: "r"(d), "r"(a), "l"(b), "r"(idesc), "r"(z), "r"(e) : "memory");
}
__device__ __forceinline__ void mma_f16_ss(uint32_t d, uint64_t a, uint64_t b,
                                           uint32_t idesc, bool en) {
    uint32_t e = en ? 1u : 0u, z = 0u;
    asm volatile("{\n\t.reg .pred p;\n\tsetp.ne.u32 p, %5, 0;\n\t"
        "tcgen05.mma.cta_group::1.kind::f16 [%0], %1, %2, %3, {%4, %4, %4, %4}, p;\n\t}"
        :: "r"(d), "l"(a), "l"(b), "r"(idesc), "r"(z), "r"(e) : "memory");
}
__device__ __forceinline__ void ldtm32(uint32_t* r, uint32_t a) {
    asm volatile("tcgen05.ld.sync.aligned.32x32b.x32.b32 "
        "{%0,%1,%2,%3,%4,%5,%6,%7,%8,%9,%10,%11,%12,%13,%14,%15,"
        "%16,%17,%18,%19,%20,%21,%22,%23,%24,%25,%26,%27,%28,%29,%30,%31}, [%32];"
        : "=r"(r[0]),"=r"(r[1]),"=r"(r[2]),"=r"(r[3]),"=r"(r[4]),"=r"(r[5]),
          "=r"(r[6]),"=r"(r[7]),"=r"(r[8]),"=r"(r[9]),"=r"(r[10]),"=r"(r[11]),
          "=r"(r[12]),"=r"(r[13]),"=r"(r[14]),"=r"(r[15]),"=r"(r[16]),"=r"(r[17]),
          "=r"(r[18]),"=r"(r[19]),"=r"(r[20]),"=r"(r[21]),"=r"(r[22]),"=r"(r[23]),
          "=r"(r[24]),"=r"(r[25]),"=r"(r[26]),"=r"(r[27]),"=r"(r[28]),"=r"(r[29]),
          "=r"(r[30]),"=r"(r[31]) : "r"(a));
}
__device__ __forceinline__ void sttm32(uint32_t a, const uint32_t* r) {
    asm volatile("tcgen05.st.sync.aligned.32x32b.x32.b32 [%0], "
        "{%1,%2,%3,%4,%5,%6,%7,%8,%9,%10,%11,%12,%13,%14,%15,%16,"
        "%17,%18,%19,%20,%21,%22,%23,%24,%25,%26,%27,%28,%29,%30,%31,%32};"
        :: "r"(a),
           "r"(r[0]),"r"(r[1]),"r"(r[2]),"r"(r[3]),"r"(r[4]),"r"(r[5]),
           "r"(r[6]),"r"(r[7]),"r"(r[8]),"r"(r[9]),"r"(r[10]),"r"(r[11]),
           "r"(r[12]),"r"(r[13]),"r"(r[14]),"r"(r[15]),"r"(r[16]),"r"(r[17]),
           "r"(r[18]),"r"(r[19]),"r"(r[20]),"r"(r[21]),"r"(r[22]),"r"(r[23]),
           "r"(r[24]),"r"(r[25]),"r"(r[26]),"r"(r[27]),"r"(r[28]),"r"(r[29]),
           "r"(r[30]),"r"(r[31]) : "memory");
}
static constexpr uint32_t MMA_IDESC =   // coarse: N=64
    (1u << 4) | (1u << 7) | (1u << 10) | (8u << 17) | (8u << 24);
static constexpr uint32_t IDESC_G =     // gemm: N=256
    (1u << 4) | (1u << 7) | (1u << 10) | (32u << 17) | (8u << 24);
#endif // HAS_TC

__device__ __forceinline__ void split3(float a, __nv_bfloat16& h, __nv_bfloat16& m,
                                       __nv_bfloat16& l) {
    h = __float2bfloat16(a);
    float r = a - __bfloat162float(h);
    m = __float2bfloat16(r);
    l = __float2bfloat16(r - __bfloat162float(m));
}
__device__ __forceinline__ uint32_t toff(int r, int k) {
    uint32_t lin = (uint32_t)(r >> 3) * 1024u + (uint32_t)(k >> 6) * 8192u
                 + (uint32_t)(r & 7) * 128u + (uint32_t)(k & 63) * 2u;
    return lin ^ ((lin >> 3) & 0x70u);
}

// ---------------- K0: W -> 3-way bf16 split ---------------------------------
__global__ void conv_w_kernel(const float* __restrict__ W)
{
    size_t base = ((size_t)blockIdx.x * 256 + threadIdx.x) * 8;
    float v[8];
    *reinterpret_cast<float4*>(v)     = *reinterpret_cast<const float4*>(W + base);
    *reinterpret_cast<float4*>(v + 4) = *reinterpret_cast<const float4*>(W + base + 4);
    __nv_bfloat16 h[8], m[8], l[8];
#pragma unroll
    for (int j = 0; j < 8; j++) split3(v[j], h[j], m[j], l[j]);
    *reinterpret_cast<uint4*>(&g_wh[base]) = *reinterpret_cast<uint4*>(h);
    *reinterpret_cast<uint4*>(&g_wm[base]) = *reinterpret_cast<uint4*>(m);
    *reinterpret_cast<uint4*>(&g_wl[base]) = *reinterpret_cast<uint4*>(l);
}

// ---------------- K1: z = x @ W^T + b  (tcgen05, 3-split bf16) ---------------
static constexpr uint32_t G_A = 0;
static constexpr uint32_t G_B = 98304;
static constexpr uint32_t G_BIAS = 196608;
static constexpr uint32_t G_MB = 197632, G_TP = 197640;
static constexpr uint32_t GSMEM_NEED = 197644 + 1040;

__global__ __launch_bounds__(256, 1)
void gemm_z_tc(const float* __restrict__ x, const float* __restrict__ W,
               const float* __restrict__ bias)
{
#if HAS_TC
    extern __shared__ char smraw[];
    uint32_t raw = smem_u32(smraw);
    uint32_t sb  = (raw + 1023u) & ~1023u;
    char* sm = smraw + (sb - raw);
    float* sbias = reinterpret_cast<float*>(sm + G_BIAS);

    const int tid = threadIdx.x;
    const int rb  = blockIdx.x * 128;

    if (tid < 32) TC_ALLOC(sb + G_TP, 256);
    if (tid == 0) MBAR_INIT(sb + G_MB, 1);
    sbias[tid] = bias[tid];
    __syncthreads();
    uint32_t tmem;
    asm volatile("ld.shared.b32 %0, [%1];" : "=r"(tmem) : "r"(sb + G_TP));

#pragma unroll
    for (int g = tid; g < 1024; g += 256) {
        int r = g >> 3, k8 = (g & 7) << 3;
        const float* src = x + (size_t)(rb + r) * DIMS + k8;
        float v[8];
        *reinterpret_cast<float4*>(v)     = *reinterpret_cast<const float4*>(src);
        *reinterpret_cast<float4*>(v + 4) = *reinterpret_cast<const float4*>(src + 4);
        __nv_bfloat16 h[8], m[8], l[8];
#pragma unroll
        for (int j = 0; j < 8; j++) split3(v[j], h[j], m[j], l[j]);
        uint32_t o = toff(r, k8);
        *reinterpret_cast<uint4*>(sm + G_A + o)         = *reinterpret_cast<uint4*>(h);
        *reinterpret_cast<uint4*>(sm + G_A + 16384 + o) = *reinterpret_cast<uint4*>(m);
        *reinterpret_cast<uint4*>(sm + G_A + 32768 + o) = *reinterpret_cast<uint4*>(l);
    }
    FENCE_ASYNC();

    for (int ch = 0; ch < 4; ++ch) {
        for (int c = tid; c < 6144; c += 256) {
            int s = c >> 11, ci = c & 2047;
            int r = ci >> 3, k8 = (ci & 7) << 3;
            const __nv_bfloat16* src =
                (s == 0 ? g_wh : s == 1 ? g_wm : g_wl) + (size_t)r * DIMS + ch * 64 + k8;
            CP_ASYNC16(sb + G_B + (uint32_t)s * 32768u + toff(r, k8), src);
        }
        CP_COMMIT(); CP_WAIT0();
        __syncthreads();

        if (tid < 32 && elect_one()) {
            TC_FENCE_A();
            uint64_t A0 = make_desc(sb + G_A + (uint32_t)(ch & 1) * 49152u);
            uint64_t A1 = A0 + 1024, A2 = A0 + 2048;
            uint64_t B0 = make_desc(sb + G_B);
            uint64_t B1 = B0 + 2048, B2 = B0 + 4096;
#pragma unroll
            for (int kk = 0; kk < 4; ++kk) {
                uint64_t off = (uint64_t)(kk * 2);
                mma_f16_ss(tmem, A0 + off, B0 + off, IDESC_G, !(ch == 0 && kk == 0));
                mma_f16_ss(tmem, A0 + off, B1 + off, IDESC_G, true);
                mma_f16_ss(tmem, A1 + off, B0 + off, IDESC_G, true);
                mma_f16_ss(tmem, A1 + off, B1 + off, IDESC_G, true);
                mma_f16_ss(tmem, A0 + off, B2 + off, IDESC_G, true);
                mma_f16_ss(tmem, A2 + off, B0 + off, IDESC_G, true);
            }
            TC_COMMIT(sb + G_MB);
        }
        if (ch < 3) {
            uint32_t abase = G_A + (uint32_t)((ch + 1) & 1) * 49152u;
#pragma unroll
            for (int g = tid; g < 1024; g += 256) {
                int r = g >> 3, k8 = (g & 7) << 3;
                const float* src = x + (size_t)(rb + r) * DIMS + (ch + 1) * 64 + k8;
                float v[8];
                *reinterpret_cast<float4*>(v)     = *reinterpret_cast<const float4*>(src);
                *reinterpret_cast<float4*>(v + 4) = *reinterpret_cast<const float4*>(src + 4);
                __nv_bfloat16 h[8], m[8], l[8];
#pragma unroll
                for (int j = 0; j < 8; j++) split3(v[j], h[j], m[j], l[j]);
                uint32_t o = toff(r, k8);
                *reinterpret_cast<uint4*>(sm + abase + o)         = *reinterpret_cast<uint4*>(h);
                *reinterpret_cast<uint4*>(sm + abase + 16384 + o) = *reinterpret_cast<uint4*>(m);
                *reinterpret_cast<uint4*>(sm + abase + 32768 + o) = *reinterpret_cast<uint4*>(l);
            }
            FENCE_ASYNC();
        }
        MBAR_WAIT(sb + G_MB, ch & 1);
        __syncthreads();
    }
    TC_FENCE_A();

    const int sub = (tid >> 5) & 3, half = tid >> 7, lane = tid & 31;
    const int row = rb + sub * 32 + lane;
    const uint32_t woff = ((uint32_t)sub) << 21;
#pragma unroll
    for (int q = 0; q < 4; ++q) {
        uint32_t regs[32];
        ldtm32(regs, tmem + half * 128 + q * 32 + woff);
        TC_WAIT_LD();
        int c0 = half * 128 + q * 32;
#pragma unroll
        for (int j = 0; j < 32; j += 4) {
            float4 v;
            v.x = __uint_as_float(regs[j+0]) + sbias[c0+j+0];
            v.y = __uint_as_float(regs[j+1]) + sbias[c0+j+1];
            v.z = __uint_as_float(regs[j+2]) + sbias[c0+j+2];
            v.w = __uint_as_float(regs[j+3]) + sbias[c0+j+3];
            *reinterpret_cast<float4*>(&g_z[(size_t)row * DIMS + c0 + j]) = v;
        }
    }
    TC_FENCE_B();
    __syncthreads();
    if (tid == 0) MBAR_INVAL(sb + G_MB);
    __syncthreads();
    if (tid < 32) { TC_RELINQ(); TC_DEALLOC(tmem, 256); }
#else
    int tid = threadIdx.x, rb = blockIdx.x * 128;
    for (int o = tid; o < 128 * DIMS; o += 256) {
        int r = rb + (o >> 8), c = o & 255;
        float acc = 0.f;
        for (int k = 0; k < DIMS; k++)
            acc += x[(size_t)r * DIMS + k] * W[(size_t)c * DIMS + k];
        g_z[(size_t)r * DIMS + c] = acc + bias[c];
    }
#endif
}

// ---------------- K2: emb -> split bf16 + code norms -------------------------
__global__ void conv_emb_kernel(const float* __restrict__ emb)
{
    int row = blockIdx.x * 8 + (threadIdx.x >> 5);
    int lane = threadIdx.x & 31;
    const float* p = &emb[(size_t)row * DIMS + lane * 8];
    float v[8];
    *reinterpret_cast<float4*>(v)     = *reinterpret_cast<const float4*>(p);
    *reinterpret_cast<float4*>(v + 4) = *reinterpret_cast<const float4*>(p + 4);
    uint4 oh, ol;
    uint32_t* ohp = reinterpret_cast<uint32_t*>(&oh);
    uint32_t* olp = reinterpret_cast<uint32_t*>(&ol);
    float s = 0.f;
#pragma unroll
    for (int j = 0; j < 4; j++) {
        float a0 = v[2*j], a1 = v[2*j+1];
        __nv_bfloat16 h0 = __float2bfloat16(a0), h1 = __float2bfloat16(a1);
        float r0 = a0 - __bfloat162float(h0), r1 = a1 - __bfloat162float(h1);
        __nv_bfloat162 hp; hp.x = h0; hp.y = h1;
        __nv_bfloat162 lp = __floats2bfloat162_rn(r0, r1);
        ohp[j] = *reinterpret_cast<uint32_t*>(&hp);
        olp[j] = *reinterpret_cast<uint32_t*>(&lp);
        s += a0*a0 + a1*a1;
    }
    *reinterpret_cast<uint4*>(&g_eh[(size_t)row * DIMS + lane * 8]) = oh;
    *reinterpret_cast<uint4*>(&g_el[(size_t)row * DIMS + lane * 8]) = ol;
#pragma unroll
    for (int ofs = 16; ofs > 0; ofs >>= 1) s += __shfl_down_sync(0xffffffffu, s, ofs);
    if (lane == 0) g_cnorm[row] = s;
}

// ---------------- K3: split-bf16 tcgen05 coarse argmin (top-2 + stream) ------
static constexpr uint32_t S_B = 0, S_CN = 131072, S_MB = 135168, S_TP = 135184;
static constexpr uint32_t SMEM_NEED = 135188 + 1024 + 12;

#if HAS_TC
__device__ __forceinline__ void load_btile_async(uint32_t sbase, int tile,
                                                 int t, int nth)
{
    const __nv_bfloat16* eh = g_eh + (size_t)tile * 64 * DIMS;
    const __nv_bfloat16* el = g_el + (size_t)tile * 64 * DIMS;
    for (int c = t; c < 4096; c += nth) {
        int part = c >> 11;
        int ci = c & 2047;
        int r = ci >> 5, k = (ci & 31) << 3;
        const __nv_bfloat16* src = (part ? el : eh) + r * DIMS + k;
        CP_ASYNC16(sbase + (uint32_t)part * 32768u + toff(r, k), src);
    }
}
#endif

__global__ __launch_bounds__(256, 1)
void coarse_kernel()
{
#if HAS_TC
    extern __shared__ char smraw[];
    uint32_t raw = smem_u32(smraw);
    uint32_t sb  = (raw + 1023u) & ~1023u;
    char* sm = smraw + (sb - raw);
    float* scn = reinterpret_cast<float*>(sm + S_CN);

    const int tid = threadIdx.x;
    const int w = tid >> 5, lane = tid & 31;
    const int sub = w & 3, half = w >> 2;
    const int rb = blockIdx.x * 128;
    const int myrow = sub * 32 + lane;
    const int rowg = rb + myrow;
    const uint32_t woff = ((uint32_t)sub) << 21;
    int* cbase = &g_cands[(size_t)rowg * CSTRIDE + half * NC_H];

    if (w == 0) TC_ALLOC(sb + S_TP, 512);
    if (tid == 0) { MBAR_INIT(sb + S_MB, 1); MBAR_INIT(sb + S_MB + 8, 1); }
#pragma unroll
    for (int i = tid; i < NCODES; i += 256) scn[i] = g_cnorm[i];
    __syncthreads();
    uint32_t tmem;
    asm volatile("ld.shared.b32 %0, [%1];" : "=r"(tmem) : "r"(sb + S_TP));

    float rn = 0.f;
    if (half == 0) {
        const float* zp = &g_z[(size_t)rowg * DIMS];
#pragma unroll
        for (int ch = 0; ch < 4; ++ch) {
            float v[64];
#pragma unroll
            for (int q = 0; q < 16; ++q)
                *reinterpret_cast<float4*>(v + q * 4) =
                    *reinterpret_cast<const float4*>(zp + ch * 64 + q * 4);
            uint32_t hi[32], lo[32];
#pragma unroll
            for (int j = 0; j < 32; ++j) {
                float a0 = v[2*j], a1 = v[2*j+1];
                rn += a0*a0 + a1*a1;
                __nv_bfloat16 h0 = __float2bfloat16(a0), h1 = __float2bfloat16(a1);
                float r0 = a0 - __bfloat162float(h0), r1 = a1 - __bfloat162float(h1);
                __nv_bfloat162 hp; hp.x = h0; hp.y = h1;
                __nv_bfloat162 lp = __floats2bfloat162_rn(r0, r1);
                hi[j] = *reinterpret_cast<uint32_t*>(&hp);
                lo[j] = *reinterpret_cast<uint32_t*>(&lp);
            }
            sttm32(tmem +       ch * 32 + woff, hi);
            sttm32(tmem + 128 + ch * 32 + woff, lo);
        }
        TC_WAIT_ST();
        TC_FENCE_B();
        g_rownorm[rowg] = rn;
    } else {
        load_btile_async(sb + S_B, 0, tid - 128, 128);
        CP_COMMIT();
    }
    __syncthreads();
    if (half == 1) rn = g_rownorm[rowg];

    float m1 = CUDART_INF_F, m2 = CUDART_INF_F;
    int i1 = 0, cnt = 0;

    for (int i = 0; i < 16; ++i) {
        const int buf = i & 1;
        CP_WAIT0();
        __syncthreads();
        if (w == 0 && elect_one()) {
            TC_FENCE_A();
            uint64_t bh = make_desc(sb + S_B + (uint32_t)buf * 65536u);
            uint64_t bl = bh + 2048;
            uint32_t D  = tmem + 256 + buf * 64;
#pragma unroll
            for (int c = 0; c < 16; ++c) {
                uint64_t off = (uint64_t)((c >> 2) * 512 + (c & 3) * 2);
                uint32_t ah = tmem + c * 8, al = tmem + 128 + c * 8;
                mma_f16_ts(D, ah, bh + off, MMA_IDESC, c > 0);
                mma_f16_ts(D, ah, bl + off, MMA_IDESC, true);
                mma_f16_ts(D, al, bh + off, MMA_IDESC, true);
            }
            TC_COMMIT(sb + S_MB + 8 * buf);
        }
        if (i >= 1) { MBAR_WAIT(sb + S_MB + 8 * (buf ^ 1), ((i - 1) >> 1) & 1); TC_FENCE_A(); }
        if (i < 15) { load_btile_async(sb + S_B + (uint32_t)(buf ^ 1) * 65536u, i + 1, tid, 256); CP_COMMIT(); }
        if (i >= 1) {
            uint32_t regs[32];
            ldtm32(regs, tmem + 256 + (buf ^ 1) * 64 + (half << 5) + woff);
            TC_WAIT_LD();
            const int col0 = (i - 1) * 64 + (half << 5);
#pragma unroll
            for (int r = 0; r < 32; ++r) {
                int col = col0 + r;
                float d = __fadd_rn(rn, scn[col]) - 2.0f * __uint_as_float(regs[r]);
                if (d < m1)      { m2 = m1; m1 = d; i1 = col; }
                else if (d < m2) { m2 = d; }
                if (d <= m1 + MARGIN) {           // append-only superset stream
                    if (cnt < NC_H) cbase[cnt] = col;
                    cnt++;
                }
            }
            TC_FENCE_B();
        }
    }
    MBAR_WAIT(sb + S_MB + 8, 1);
    TC_FENCE_A();
    {
        uint32_t regs[32];
        ldtm32(regs, tmem + 256 + 64 + (half << 5) + woff);
        TC_WAIT_LD();
        const int col0 = 15 * 64 + (half << 5);
#pragma unroll
        for (int r = 0; r < 32; ++r) {
            int col = col0 + r;
            float d = __fadd_rn(rn, scn[col]) - 2.0f * __uint_as_float(regs[r]);
            if (d < m1)      { m2 = m1; m1 = d; i1 = col; }
            else if (d < m2) { m2 = d; }
            if (d <= m1 + MARGIN) {
                if (cnt < NC_H) cbase[cnt] = col;
                cnt++;
            }
        }
    }
    TC_FENCE_B();

    // ---- merge halves: each half writes (m1,i1,m2,cnt) -> 4 slots -----------
    {
        float* blk = reinterpret_cast<float*>(sm + S_B) + (myrow * 2 + half) * 4;
        blk[0] = m1;
        reinterpret_cast<int*>(blk)[1] = i1;
        blk[2] = m2;
        reinterpret_cast<int*>(blk)[3] = cnt;
    }
    __syncthreads();
    if (half == 0) {
        float* A = reinterpret_cast<float*>(sm + S_B) + (myrow * 2) * 4;
        float* B = A + 4;
        float m1A = A[0], m2A = A[2], m1B = B[0], m2B = B[2];
        int i1A = reinterpret_cast<int*>(A)[1], i1B = reinterpret_cast<int*>(B)[1];
        int cA = reinterpret_cast<int*>(A)[3], cB = reinterpret_cast<int*>(B)[3];
        bool takeB = (m1B < m1A) || (m1B == m1A && i1B < i1A);
        float gm0 = takeB ? m1B : m1A;
        int   gi0 = takeB ? i1B : i1A;
        float other = takeB ? m1A : m1B;
        float m2w  = takeB ? m2B : m2A;
        float second = fminf(other, m2w);
        g_idx[rowg] = gi0;
        if (cA > NC_H || cB > NC_H) g_ccount[rowg] = -1;        // overflow
        else if (second > gm0 + MARGIN) g_ccount[rowg] = 0;     // decided
        else g_ccount[rowg] = cA | (cB << 8);                   // recheck lists
    }
    __syncthreads();
    if (tid == 0) { MBAR_INVAL(sb + S_MB); MBAR_INVAL(sb + S_MB + 8); }
    __syncthreads();
    if (w == 0) { TC_RELINQ(); TC_DEALLOC(tmem, 512); }
#else
    int r = blockIdx.x * 128 + (int)threadIdx.x;
    if (threadIdx.x < 128) {
        float s = 0.f;
        for (int i = 0; i < DIMS; i++) { float v = g_z[(size_t)r * DIMS + i]; s += v * v; }
        g_rownorm[r] = s;
        g_idx[r] = 0;
        g_ccount[r] = -1;
    }
#endif
}

// ---------------- K4a: exact fp32 recheck of candidate lists -----------------
__global__ __launch_bounds__(256)
void recheck_kernel(const float* __restrict__ emb)
{
    int row  = blockIdx.x * 8 + (threadIdx.x >> 5);
    int lane = threadIdx.x & 31;
    int cc   = g_ccount[row];
    if (cc <= 0) return;   // 0 = decided, -1 = handled by recheck_full
    int cntA = cc & 0xff, cntB = (cc >> 8) & 0xff;

    const float* zp = &g_z[(size_t)row * DIMS];
    float zv[8];
#pragma unroll
    for (int i = 0; i < 8; i++) zv[i] = zp[lane + 32 * i];
    float rn = g_rownorm[row];
    const int* cl = &g_cands[(size_t)row * CSTRIDE];

    float bv = CUDART_INF_F;
    int   bi = 0x7fffffff;
    for (int c = 0; c < cntA + cntB; c++) {
        int idx = (c < cntA) ? cl[c] : cl[NC_H + c - cntA];
        const float* ep = &emb[(size_t)idx * DIMS];
        float dot = 0.f;
#pragma unroll
        for (int i = 0; i < 8; i++) dot += zv[i] * ep[lane + 32 * i];
#pragma unroll
        for (int o = 16; o > 0; o >>= 1) dot += __shfl_down_sync(0xffffffffu, dot, o);
        if (lane == 0) {
            float t = __fadd_rn(rn, g_cnorm[idx]);
            float dist = __fadd_rn(t, -__fmul_rn(2.0f, dot));
            if (dist < bv || (dist == bv && idx < bi)) { bv = dist; bi = idx; }
        }
    }
    if (lane == 0) g_idx[row] = bi;
}

// ---------------- K4b: fast exact full scan for overflow rows (rare) ---------
__global__ __launch_bounds__(256)
void recheck_full_kernel(const float* __restrict__ emb)
{
    int row = blockIdx.x;
    if (g_ccount[row] != -1) return;

    __shared__ float sz[DIMS];
    __shared__ float sv[256];
    __shared__ int   si[256];
    int t = threadIdx.x;
    sz[t] = g_z[(size_t)row * DIMS + t];
    float rn = g_rownorm[row];
    __syncthreads();

    float best = CUDART_INF_F;
    int   bi = 0x7fffffff;
#pragma unroll
    for (int q = 0; q < 4; q++) {
        int c = q * 256 + t;
        const float* ep = &emb[(size_t)c * DIMS];
        float d0 = 0.f, d1 = 0.f, d2 = 0.f, d3 = 0.f;
#pragma unroll 8
        for (int i = 0; i < DIMS; i += 4) {
            d0 += sz[i+0] * ep[i+0];
            d1 += sz[i+1] * ep[i+1];
            d2 += sz[i+2] * ep[i+2];
            d3 += sz[i+3] * ep[i+3];
        }
        float dot = (d0 + d1) + (d2 + d3);
        float dist = __fadd_rn(__fadd_rn(rn, g_cnorm[c]), -__fmul_rn(2.0f, dot));
        if (dist < best || (dist == best && c < bi)) { best = dist; bi = c; }
    }
    sv[t] = best; si[t] = bi;
    __syncthreads();
    for (int o = 128; o > 0; o >>= 1) {
        if (t < o) {
            if (sv[t+o] < sv[t] || (sv[t+o] == sv[t] && si[t+o] < si[t])) {
                sv[t] = sv[t+o]; si[t] = si[t+o];
            }
        }
        __syncthreads();
    }
    if (t == 0) g_idx[row] = si[0];
}

// ---------------- K5: gather + per-row loss -----------------------------------
__global__ void gather_kernel(const float* __restrict__ emb,
                              float* __restrict__ outq, float* __restrict__ outi)
{
    __shared__ float ws[8];
    int row = blockIdx.x, d = threadIdx.x;
    int idx = g_idx[row];
    float e = emb[(size_t)idx * DIMS + d];
    float z = g_z[(size_t)row * DIMS + d];
    outq[(size_t)row * DIMS + d] = e;
    float diff = e - z;
    float s = diff * diff;
#pragma unroll
    for (int o = 16; o > 0; o >>= 1) s += __shfl_down_sync(0xffffffffu, s, o);
    int lane = d & 31, w = d >> 5;
    if (lane == 0) ws[w] = s;
    __syncthreads();
    if (d == 0) {
        float tot = 0.f;
#pragma unroll
        for (int i = 0; i < 8; i++) tot += ws[i];
        g_rowloss[row] = tot;
        outi[row] = (float)idx;
    }
}

// ---------------- K6: loss reduction ------------------------------------------
__global__ void loss_kernel(float* __restrict__ outl)
{
    __shared__ double sd[256];
    double s = 0.0;
    for (int i = threadIdx.x; i < M_ROWS; i += 256) s += (double)g_rowloss[i];
    sd[threadIdx.x] = s;
    __syncthreads();
    for (int o = 128; o > 0; o >>= 1) {
        if (threadIdx.x < o) sd[threadIdx.x] += sd[threadIdx.x + o];
        __syncthreads();
    }
    if (threadIdx.x == 0) outl[0] = (float)(1.25 * sd[0] / 8388608.0);
}

// ---------------- launch --------------------------------------------------------
extern "C" void kernel_launch(void* const* d_in, const int* in_sizes, int n_in,
                              void* d_out, int out_size)
{
    const float* x   = (const float*)d_in[0];
    const float* W   = (const float*)d_in[1];
    const float* b   = (const float*)d_in[2];
    const float* emb = (const float*)d_in[3];

    float* out  = (float*)d_out;
    float* outq = out;
    float* outi = out + (size_t)M_ROWS * DIMS;
    float* outl = outi + M_ROWS;

    static int smem_set = 0;
    if (!smem_set) {
        cudaFuncSetAttribute(coarse_kernel, cudaFuncAttributeMaxDynamicSharedMemorySize, SMEM_NEED);
        cudaFuncSetAttribute(gemm_z_tc, cudaFuncAttributeMaxDynamicSharedMemorySize, GSMEM_NEED);
        smem_set = 1;
    }

    conv_w_kernel<<<32, 256>>>(W);
    conv_emb_kernel<<<NCODES / 8, 256>>>(emb);
    gemm_z_tc<<<M_ROWS / 128, 256, GSMEM_NEED>>>(x, W, b);
    coarse_kernel<<<M_ROWS / 128, 256, SMEM_NEED>>>();
    recheck_kernel<<<M_ROWS / 8, 256>>>(emb);
    recheck_full_kernel<<<M_ROWS, 256>>>(emb);
    gather_kernel<<<M_ROWS, 256>>>(emb, outq, outi);
    loss_kernel<<<1, 256>>>(outl);
}

// round 12
// speedup vs baseline: 3.0319x; 1.1145x over previous
#include <cuda_runtime.h>
#include <cuda.h>
#include <cuda_bf16.h>
#include <math_constants.h>
#include <cstdint>

#define M_ROWS 32768
#define DIMS   256
#define NCODES 1024
#define NC_H   24
#define CSTRIDE 48
#define MARGIN 2.5e-4f

#if defined(__CUDA_ARCH_FEAT_SM103_ALL) || defined(__CUDA_ARCH_FEAT_SM100_ALL) || defined(__CUDA_ARCH_FEAT_SM101_ALL)
#define HAS_TC 1
#else
#define HAS_TC 0
#endif

// ---------------- device-global scratch ------------------------------------
__device__ float g_z[M_ROWS * DIMS];
__device__ __align__(128) __nv_bfloat16 g_wh[DIMS * DIMS];
__device__ __align__(128) __nv_bfloat16 g_wm[DIMS * DIMS];
__device__ __align__(128) __nv_bfloat16 g_wl[DIMS * DIMS];
__device__ __align__(128) __nv_bfloat16 g_eh[NCODES * DIMS];
__device__ __align__(128) __nv_bfloat16 g_el[NCODES * DIMS];
__device__ float g_cnorm[NCODES];
__device__ float g_rownorm[M_ROWS];
__device__ int   g_idx[M_ROWS];
__device__ float g_rowloss[M_ROWS];
__device__ int   g_cands[(size_t)M_ROWS * CSTRIDE];
__device__ int   g_ccount[M_ROWS];

// ---------------- PTX helpers ------------------------------------------------
__device__ __forceinline__ uint32_t smem_u32(const void* p) {
    uint32_t a;
    asm("{ .reg .u64 t; cvta.to.shared.u64 t, %1; cvt.u32.u64 %0, t; }" : "=r"(a) : "l"(p));
    return a;
}
#define FENCE_ASYNC()    asm volatile("fence.proxy.async.shared::cta;" ::: "memory")
#define MBAR_INIT(mb, c) asm volatile("mbarrier.init.shared.b64 [%0], %1;" :: "r"(mb), "r"(c) : "memory")
#define MBAR_INVAL(mb)   asm volatile("mbarrier.inval.shared.b64 [%0];" :: "r"(mb) : "memory")
#define MBAR_EXPECT_TX(mb, bytes) \
    asm volatile("mbarrier.arrive.expect_tx.shared.b64 _, [%0], %1;" :: "r"(mb), "r"(bytes) : "memory")
#define TMA2D(smem, mapptr, cx, cy, mbar) \
    asm volatile("cp.async.bulk.tensor.2d.shared::cta.global.tile.mbarrier::complete_tx::bytes " \
        "[%0], [%1, {%2, %3}], [%4];" \
        :: "r"((uint32_t)(smem)), "l"(mapptr), "r"((int)(cx)), "r"((int)(cy)), \
           "r"((uint32_t)(mbar)) : "memory")
#define MBAR_WAIT(mb, ph) do {                                                 \
    uint32_t _m = (mb), _p = (ph), _d;                                         \
    asm volatile("{\n\t.reg .pred p;\n\t"                                      \
        "mbarrier.try_wait.parity.acquire.cta.shared::cta.b64 p, [%1], %2;\n\t"\
        "selp.b32 %0, 1, 0, p;\n\t}" : "=r"(_d) : "r"(_m), "r"(_p) : "memory");\
    if (!_d) {                                                                 \
        asm volatile("{\n\t.reg .pred P1;\n\tWL_%=:\n\t"                       \
            "mbarrier.try_wait.parity.acquire.cta.shared::cta.b64 P1, [%0], %1, 0x989680;\n\t" \
            "@P1 bra.uni WD_%=;\n\tbra.uni WL_%=;\n\tWD_%=:\n\t}"              \
            :: "r"(_m), "r"(_p) : "memory");                                   \
    }                                                                          \
} while (0)

#if HAS_TC
__device__ __forceinline__ uint32_t elect_one() {
    uint32_t p;
    asm volatile("{\n\t.reg .pred p;\n\telect.sync _|p, 0xFFFFFFFF;\n\t"
                 "selp.b32 %0, 1, 0, p;\n\t}" : "=r"(p));
    return p;
}
#define TC_ALLOC(sa, n)  asm volatile("tcgen05.alloc.cta_group::1.sync.aligned.shared::cta.b32 [%0], %1;" :: "r"(sa), "r"(n) : "memory")
#define TC_RELINQ()      asm volatile("tcgen05.relinquish_alloc_permit.cta_group::1.sync.aligned;")
#define TC_DEALLOC(t, n) asm volatile("tcgen05.dealloc.cta_group::1.sync.aligned.b32 %0, %1;" :: "r"(t), "r"(n))
#define TC_COMMIT(mb)    asm volatile("tcgen05.commit.cta_group::1.mbarrier::arrive::one.shared::cluster.b64 [%0];" :: "r"(mb) : "memory")
#define TC_WAIT_LD()     asm volatile("tcgen05.wait::ld.sync.aligned;" ::: "memory")
#define TC_WAIT_ST()     asm volatile("tcgen05.wait::st.sync.aligned;" ::: "memory")
#define TC_FENCE_B()     asm volatile("tcgen05.fence::before_thread_sync;" ::: "memory")
#define TC_FENCE_A()     asm volatile("tcgen05.fence::after_thread_sync;" ::: "memory")

static constexpr uint64_t DESC_SW128 =
    (uint64_t(2) << 61) | (uint64_t(1) << 46) | (uint64_t(64) << 32) | (uint64_t(1) << 16);
__device__ __forceinline__ uint64_t make_desc(uint32_t a) {
    return DESC_SW128 | ((uint64_t)(a >> 4) & 0x3FFF);
}
__device__ __forceinline__ void mma_f16_ts(uint32_t d, uint32_t a, uint64_t b,
                                           uint32_t idesc, bool en) {
    uint32_t e = en ? 1u : 0u, z = 0u;
    asm volatile("{\n\t.reg .pred p;\n\tsetp.ne.u32 p, %5, 0;\n\t"
        "tcgen05.mma.cta_group::1.kind::f16 [%0], [%1], %2, %3, {%4, %4, %4, %4}, p;\n\t}"
        :: "r"(d), "r"(a), "l"(b), "r"(idesc), "r"(z), "r"(e) : "memory");
}
__device__ __forceinline__ void mma_f16_ss(uint32_t d, uint64_t a, uint64_t b,
                                           uint32_t idesc, bool en) {
    uint32_t e = en ? 1u : 0u, z = 0u;
    asm volatile("{\n\t.reg .pred p;\n\tsetp.ne.u32 p, %5, 0;\n\t"
        "tcgen05.mma.cta_group::1.kind::f16 [%0], %1, %2, %3, {%4, %4, %4, %4}, p;\n\t}"
        :: "r"(d), "l"(a), "l"(b), "r"(idesc), "r"(z), "r"(e) : "memory");
}
__device__ __forceinline__ void ldtm32(uint32_t* r, uint32_t a) {
    asm volatile("tcgen05.ld.sync.aligned.32x32b.x32.b32 "
        "{%0,%1,%2,%3,%4,%5,%6,%7,%8,%9,%10,%11,%12,%13,%14,%15,"
        "%16,%17,%18,%19,%20,%21,%22,%23,%24,%25,%26,%27,%28,%29,%30,%31}, [%32];"
        : "=r"(r[0]),"=r"(r[1]),"=r"(r[2]),"=r"(r[3]),"=r"(r[4]),"=r"(r[5]),
          "=r"(r[6]),"=r"(r[7]),"=r"(r[8]),"=r"(r[9]),"=r"(r[10]),"=r"(r[11]),
          "=r"(r[12]),"=r"(r[13]),"=r"(r[14]),"=r"(r[15]),"=r"(r[16]),"=r"(r[17]),
          "=r"(r[18]),"=r"(r[19]),"=r"(r[20]),"=r"(r[21]),"=r"(r[22]),"=r"(r[23]),
          "=r"(r[24]),"=r"(r[25]),"=r"(r[26]),"=r"(r[27]),"=r"(r[28]),"=r"(r[29]),
          "=r"(r[30]),"=r"(r[31]) : "r"(a));
}
__device__ __forceinline__ void sttm32(uint32_t a, const uint32_t* r) {
    asm volatile("tcgen05.st.sync.aligned.32x32b.x32.b32 [%0], "
        "{%1,%2,%3,%4,%5,%6,%7,%8,%9,%10,%11,%12,%13,%14,%15,%16,"
        "%17,%18,%19,%20,%21,%22,%23,%24,%25,%26,%27,%28,%29,%30,%31,%32};"
        :: "r"(a),
           "r"(r[0]),"r"(r[1]),"r"(r[2]),"r"(r[3]),"r"(r[4]),"r"(r[5]),
           "r"(r[6]),"r"(r[7]),"r"(r[8]),"r"(r[9]),"r"(r[10]),"r"(r[11]),
           "r"(r[12]),"r"(r[13]),"r"(r[14]),"r"(r[15]),"r"(r[16]),"r"(r[17]),
           "r"(r[18]),"r"(r[19]),"r"(r[20]),"r"(r[21]),"r"(r[22]),"r"(r[23]),
           "r"(r[24]),"r"(r[25]),"r"(r[26]),"r"(r[27]),"r"(r[28]),"r"(r[29]),
           "r"(r[30]),"r"(r[31]) : "memory");
}
static constexpr uint32_t MMA_IDESC =
    (1u << 4) | (1u << 7) | (1u << 10) | (8u << 17) | (8u << 24);
static constexpr uint32_t IDESC_G =
    (1u << 4) | (1u << 7) | (1u << 10) | (32u << 17) | (8u << 24);
#endif // HAS_TC

__device__ __forceinline__ void split3(float a, __nv_bfloat16& h, __nv_bfloat16& m,
                                       __nv_bfloat16& l) {
    h = __float2bfloat16(a);
    float r = a - __bfloat162float(h);
    m = __float2bfloat16(r);
    l = __float2bfloat16(r - __bfloat162float(m));
}
__device__ __forceinline__ uint32_t toff(int r, int k) {
    uint32_t lin = (uint32_t)(r >> 3) * 1024u + (uint32_t)(k >> 6) * 8192u
                 + (uint32_t)(r & 7) * 128u + (uint32_t)(k & 63) * 2u;
    return lin ^ ((lin >> 3) & 0x70u);
}

// ---------------- K0: W -> 3-way bf16 split ---------------------------------
__global__ void conv_w_kernel(const float* __restrict__ W)
{
    size_t base = ((size_t)blockIdx.x * 256 + threadIdx.x) * 8;
    float v[8];
    *reinterpret_cast<float4*>(v)     = *reinterpret_cast<const float4*>(W + base);
    *reinterpret_cast<float4*>(v + 4) = *reinterpret_cast<const float4*>(W + base + 4);
    __nv_bfloat16 h[8], m[8], l[8];
#pragma unroll
    for (int j = 0; j < 8; j++) split3(v[j], h[j], m[j], l[j]);
    *reinterpret_cast<uint4*>(&g_wh[base]) = *reinterpret_cast<uint4*>(h);
    *reinterpret_cast<uint4*>(&g_wm[base]) = *reinterpret_cast<uint4*>(m);
    *reinterpret_cast<uint4*>(&g_wl[base]) = *reinterpret_cast<uint4*>(l);
}

// ---------------- K1: z = x @ W^T + b  (tcgen05, 3-split bf16, TMA B) --------
static constexpr uint32_t G_A = 0;
static constexpr uint32_t G_B = 98304;
static constexpr uint32_t G_BIAS = 196608;
static constexpr uint32_t G_MB = 197632, G_FB = 197648, G_TP = 197664;
static constexpr uint32_t GSMEM_NEED = 197668 + 1040;

__global__ __launch_bounds__(256, 1)
void gemm_z_tc(const float* __restrict__ x, const float* __restrict__ W,
               const float* __restrict__ bias,
               const __grid_constant__ CUtensorMap mwh,
               const __grid_constant__ CUtensorMap mwm,
               const __grid_constant__ CUtensorMap mwl)
{
#if HAS_TC
    extern __shared__ char smraw[];
    uint32_t raw = smem_u32(smraw);
    uint32_t sb  = (raw + 1023u) & ~1023u;
    char* sm = smraw + (sb - raw);
    float* sbias = reinterpret_cast<float*>(sm + G_BIAS);

    const int tid = threadIdx.x;
    const int rb  = blockIdx.x * 128;

    if (tid < 32) TC_ALLOC(sb + G_TP, 256);
    if (tid == 0) { MBAR_INIT(sb + G_MB, 1); MBAR_INIT(sb + G_FB, 1); }
    sbias[tid] = bias[tid];
    __syncthreads();
    uint32_t tmem;
    asm volatile("ld.shared.b32 %0, [%1];" : "=r"(tmem) : "r"(sb + G_TP));

    if (tid == 0) {
        MBAR_EXPECT_TX(sb + G_FB, 98304);
        TMA2D(sb + G_B,         &mwh, 0, 0, sb + G_FB);
        TMA2D(sb + G_B + 32768, &mwm, 0, 0, sb + G_FB);
        TMA2D(sb + G_B + 65536, &mwl, 0, 0, sb + G_FB);
    }
    // stage A chunk 0
#pragma unroll
    for (int g = tid; g < 1024; g += 256) {
        int r = g >> 3, k8 = (g & 7) << 3;
        const float* src = x + (size_t)(rb + r) * DIMS + k8;
        float v[8];
        *reinterpret_cast<float4*>(v)     = *reinterpret_cast<const float4*>(src);
        *reinterpret_cast<float4*>(v + 4) = *reinterpret_cast<const float4*>(src + 4);
        __nv_bfloat16 h[8], m[8], l[8];
#pragma unroll
        for (int j = 0; j < 8; j++) split3(v[j], h[j], m[j], l[j]);
        uint32_t o = toff(r, k8);
        *reinterpret_cast<uint4*>(sm + G_A + o)         = *reinterpret_cast<uint4*>(h);
        *reinterpret_cast<uint4*>(sm + G_A + 16384 + o) = *reinterpret_cast<uint4*>(m);
        *reinterpret_cast<uint4*>(sm + G_A + 32768 + o) = *reinterpret_cast<uint4*>(l);
    }
    FENCE_ASYNC();
    __syncthreads();

    for (int ch = 0; ch < 4; ++ch) {
        if (tid < 32 && elect_one()) {
            MBAR_WAIT(sb + G_FB, ch & 1);
            TC_FENCE_A();
            uint64_t A0 = make_desc(sb + G_A + (uint32_t)(ch & 1) * 49152u);
            uint64_t A1 = A0 + 1024, A2 = A0 + 2048;
            uint64_t B0 = make_desc(sb + G_B);
            uint64_t B1 = B0 + 2048, B2 = B0 + 4096;
#pragma unroll
            for (int kk = 0; kk < 4; ++kk) {
                uint64_t off = (uint64_t)(kk * 2);
                mma_f16_ss(tmem, A0 + off, B0 + off, IDESC_G, !(ch == 0 && kk == 0));
                mma_f16_ss(tmem, A0 + off, B1 + off, IDESC_G, true);
                mma_f16_ss(tmem, A1 + off, B0 + off, IDESC_G, true);
                mma_f16_ss(tmem, A1 + off, B1 + off, IDESC_G, true);
                mma_f16_ss(tmem, A0 + off, B2 + off, IDESC_G, true);
                mma_f16_ss(tmem, A2 + off, B0 + off, IDESC_G, true);
            }
            TC_COMMIT(sb + G_MB);
        }
        if (ch < 3) {
            uint32_t abase = G_A + (uint32_t)((ch + 1) & 1) * 49152u;
#pragma unroll
            for (int g = tid; g < 1024; g += 256) {
                int r = g >> 3, k8 = (g & 7) << 3;
                const float* src = x + (size_t)(rb + r) * DIMS + (ch + 1) * 64 + k8;
                float v[8];
                *reinterpret_cast<float4*>(v)     = *reinterpret_cast<const float4*>(src);
                *reinterpret_cast<float4*>(v + 4) = *reinterpret_cast<const float4*>(src + 4);
                __nv_bfloat16 h[8], m[8], l[8];
#pragma unroll
                for (int j = 0; j < 8; j++) split3(v[j], h[j], m[j], l[j]);
                uint32_t o = toff(r, k8);
                *reinterpret_cast<uint4*>(sm + abase + o)         = *reinterpret_cast<uint4*>(h);
                *reinterpret_cast<uint4*>(sm + abase + 16384 + o) = *reinterpret_cast<uint4*>(m);
                *reinterpret_cast<uint4*>(sm + abase + 32768 + o) = *reinterpret_cast<uint4*>(l);
            }
            FENCE_ASYNC();
        }
        MBAR_WAIT(sb + G_MB, ch & 1);
        if (tid == 0 && ch < 3) {
            MBAR_EXPECT_TX(sb + G_FB, 98304);
            TMA2D(sb + G_B,         &mwh, (ch + 1) * 64, 0, sb + G_FB);
            TMA2D(sb + G_B + 32768, &mwm, (ch + 1) * 64, 0, sb + G_FB);
            TMA2D(sb + G_B + 65536, &mwl, (ch + 1) * 64, 0, sb + G_FB);
        }
        __syncthreads();
    }
    TC_FENCE_A();

    const int sub = (tid >> 5) & 3, half = tid >> 7, lane = tid & 31;
    const int row = rb + sub * 32 + lane;
    const uint32_t woff = ((uint32_t)sub) << 21;
#pragma unroll
    for (int q = 0; q < 4; ++q) {
        uint32_t regs[32];
        ldtm32(regs, tmem + half * 128 + q * 32 + woff);
        TC_WAIT_LD();
        int c0 = half * 128 + q * 32;
#pragma unroll
        for (int j = 0; j < 32; j += 4) {
            float4 v;
            v.x = __uint_as_float(regs[j+0]) + sbias[c0+j+0];
            v.y = __uint_as_float(regs[j+1]) + sbias[c0+j+1];
            v.z = __uint_as_float(regs[j+2]) + sbias[c0+j+2];
            v.w = __uint_as_float(regs[j+3]) + sbias[c0+j+3];
            *reinterpret_cast<float4*>(&g_z[(size_t)row * DIMS + c0 + j]) = v;
        }
    }
    TC_FENCE_B();
    __syncthreads();
    if (tid == 0) { MBAR_INVAL(sb + G_MB); MBAR_INVAL(sb + G_FB); }
    __syncthreads();
    if (tid < 32) { TC_RELINQ(); TC_DEALLOC(tmem, 256); }
#else
    int tid = threadIdx.x, rb = blockIdx.x * 128;
    for (int o = tid; o < 128 * DIMS; o += 256) {
        int r = rb + (o >> 8), c = o & 255;
        float acc = 0.f;
        for (int k = 0; k < DIMS; k++)
            acc += x[(size_t)r * DIMS + k] * W[(size_t)c * DIMS + k];
        g_z[(size_t)r * DIMS + c] = acc + bias[c];
    }
#endif
}

// ---------------- K2: emb -> split bf16 + code norms -------------------------
__global__ void conv_emb_kernel(const float* __restrict__ emb)
{
    int row = blockIdx.x * 8 + (threadIdx.x >> 5);
    int lane = threadIdx.x & 31;
    const float* p = &emb[(size_t)row * DIMS + lane * 8];
    float v[8];
    *reinterpret_cast<float4*>(v)     = *reinterpret_cast<const float4*>(p);
    *reinterpret_cast<float4*>(v + 4) = *reinterpret_cast<const float4*>(p + 4);
    uint4 oh, ol;
    uint32_t* ohp = reinterpret_cast<uint32_t*>(&oh);
    uint32_t* olp = reinterpret_cast<uint32_t*>(&ol);
    float s = 0.f;
#pragma unroll
    for (int j = 0; j < 4; j++) {
        float a0 = v[2*j], a1 = v[2*j+1];
        __nv_bfloat16 h0 = __float2bfloat16(a0), h1 = __float2bfloat16(a1);
        float r0 = a0 - __bfloat162float(h0), r1 = a1 - __bfloat162float(h1);
        __nv_bfloat162 hp; hp.x = h0; hp.y = h1;
        __nv_bfloat162 lp = __floats2bfloat162_rn(r0, r1);
        ohp[j] = *reinterpret_cast<uint32_t*>(&hp);
        olp[j] = *reinterpret_cast<uint32_t*>(&lp);
        s += a0*a0 + a1*a1;
    }
    *reinterpret_cast<uint4*>(&g_eh[(size_t)row * DIMS + lane * 8]) = oh;
    *reinterpret_cast<uint4*>(&g_el[(size_t)row * DIMS + lane * 8]) = ol;
#pragma unroll
    for (int ofs = 16; ofs > 0; ofs >>= 1) s += __shfl_down_sync(0xffffffffu, s, ofs);
    if (lane == 0) g_cnorm[row] = s;
}

// ---------------- K3: split-bf16 tcgen05 coarse argmin (TMA B loads) ---------
static constexpr uint32_t S_B = 0, S_CN = 131072, S_MB = 135168, S_TP = 135232;
static constexpr uint32_t SMEM_NEED = 135236 + 1040;

__global__ __launch_bounds__(256, 1)
void coarse_kernel(const __grid_constant__ CUtensorMap meh,
                   const __grid_constant__ CUtensorMap mel)
{
#if HAS_TC
    extern __shared__ char smraw[];
    uint32_t raw = smem_u32(smraw);
    uint32_t sb  = (raw + 1023u) & ~1023u;
    char* sm = smraw + (sb - raw);
    float* scn = reinterpret_cast<float*>(sm + S_CN);

    const int tid = threadIdx.x;
    const int w = tid >> 5, lane = tid & 31;
    const int sub = w & 3, half = w >> 2;
    const int rb = blockIdx.x * 128;
    const int myrow = sub * 32 + lane;
    const int rowg = rb + myrow;
    const uint32_t woff = ((uint32_t)sub) << 21;
    int* cbase = &g_cands[(size_t)rowg * CSTRIDE + half * NC_H];
    const uint32_t MB0 = sb + S_MB, MB1 = sb + S_MB + 8;
    const uint32_t FB0 = sb + S_MB + 16, FB1 = sb + S_MB + 24;

    if (w == 0) TC_ALLOC(sb + S_TP, 512);
    if (tid == 0) { MBAR_INIT(MB0, 1); MBAR_INIT(MB1, 1); MBAR_INIT(FB0, 1); MBAR_INIT(FB1, 1); }
#pragma unroll
    for (int i = tid; i < NCODES; i += 256) scn[i] = g_cnorm[i];
    __syncthreads();
    uint32_t tmem;
    asm volatile("ld.shared.b32 %0, [%1];" : "=r"(tmem) : "r"(sb + S_TP));

    if (tid == 0) {   // prefetch tiles 0 and 1 via TMA
        MBAR_EXPECT_TX(FB0, 65536);
#pragma unroll
        for (int kc = 0; kc < 4; ++kc) {
            TMA2D(sb + S_B + kc * 8192,         &meh, kc * 64, 0, FB0);
            TMA2D(sb + S_B + 32768 + kc * 8192, &mel, kc * 64, 0, FB0);
        }
        MBAR_EXPECT_TX(FB1, 65536);
#pragma unroll
        for (int kc = 0; kc < 4; ++kc) {
            TMA2D(sb + S_B + 65536 + kc * 8192,         &meh, kc * 64, 64, FB1);
            TMA2D(sb + S_B + 65536 + 32768 + kc * 8192, &mel, kc * 64, 64, FB1);
        }
    }

    float rn = 0.f;
    if (half == 0) {
        const float* zp = &g_z[(size_t)rowg * DIMS];
#pragma unroll
        for (int ch = 0; ch < 4; ++ch) {
            float v[64];
#pragma unroll
            for (int q = 0; q < 16; ++q)
                *reinterpret_cast<float4*>(v + q * 4) =
                    *reinterpret_cast<const float4*>(zp + ch * 64 + q * 4);
            uint32_t hi[32], lo[32];
#pragma unroll
            for (int j = 0; j < 32; ++j) {
                float a0 = v[2*j], a1 = v[2*j+1];
                rn += a0*a0 + a1*a1;
                __nv_bfloat16 h0 = __float2bfloat16(a0), h1 = __float2bfloat16(a1);
                float r0 = a0 - __bfloat162float(h0), r1 = a1 - __bfloat162float(h1);
                __nv_bfloat162 hp; hp.x = h0; hp.y = h1;
                __nv_bfloat162 lp = __floats2bfloat162_rn(r0, r1);
                hi[j] = *reinterpret_cast<uint32_t*>(&hp);
                lo[j] = *reinterpret_cast<uint32_t*>(&lp);
            }
            sttm32(tmem +       ch * 32 + woff, hi);
            sttm32(tmem + 128 + ch * 32 + woff, lo);
        }
        TC_WAIT_ST();
        TC_FENCE_B();
        g_rownorm[rowg] = rn;
    }
    __syncthreads();
    if (half == 1) rn = g_rownorm[rowg];

    float m1 = CUDART_INF_F, m2 = CUDART_INF_F;
    int i1 = 0, cnt = 0;

    for (int i = 0; i < 16; ++i) {
        const int buf = i & 1;
        if (w == 0 && elect_one()) {
            MBAR_WAIT(buf ? FB1 : FB0, (i >> 1) & 1);
            TC_FENCE_A();
            uint64_t bh = make_desc(sb + S_B + (uint32_t)buf * 65536u);
            uint64_t bl = bh + 2048;
            uint32_t D  = tmem + 256 + buf * 64;
#pragma unroll
            for (int c = 0; c < 16; ++c) {
                uint64_t off = (uint64_t)((c >> 2) * 512 + (c & 3) * 2);
                uint32_t ah = tmem + c * 8, al = tmem + 128 + c * 8;
                mma_f16_ts(D, ah, bh + off, MMA_IDESC, c > 0);
                mma_f16_ts(D, ah, bl + off, MMA_IDESC, true);
                mma_f16_ts(D, al, bh + off, MMA_IDESC, true);
            }
            TC_COMMIT(buf ? MB1 : MB0);
        }
        if (i >= 1) {
            MBAR_WAIT((buf ^ 1) ? MB1 : MB0, ((i - 1) >> 1) & 1);
            TC_FENCE_A();
            if (tid == 0 && i < 15) {   // tile i+1 -> buffer buf^1 (now free)
                uint32_t fb = (buf ^ 1) ? FB1 : FB0;
                MBAR_EXPECT_TX(fb, 65536);
#pragma unroll
                for (int kc = 0; kc < 4; ++kc) {
                    TMA2D(sb + S_B + (uint32_t)(buf ^ 1) * 65536u + kc * 8192,
                          &meh, kc * 64, (i + 1) * 64, fb);
                    TMA2D(sb + S_B + (uint32_t)(buf ^ 1) * 65536u + 32768 + kc * 8192,
                          &mel, kc * 64, (i + 1) * 64, fb);
                }
            }
            uint32_t regs[32];
            ldtm32(regs, tmem + 256 + (buf ^ 1) * 64 + (half << 5) + woff);
            TC_WAIT_LD();
            const int col0 = (i - 1) * 64 + (half << 5);
#pragma unroll
            for (int r = 0; r < 32; ++r) {
                int col = col0 + r;
                float d = __fadd_rn(rn, scn[col]) - 2.0f * __uint_as_float(regs[r]);
                if (d < m1)      { m2 = m1; m1 = d; i1 = col; }
                else if (d < m2) { m2 = d; }
                if (d <= m1 + MARGIN) {
                    if (cnt < NC_H) cbase[cnt] = col;
                    cnt++;
                }
            }
            TC_FENCE_B();
        }
        __syncthreads();
    }
    MBAR_WAIT(MB1, 1);
    TC_FENCE_A();
    {
        uint32_t regs[32];
        ldtm32(regs, tmem + 256 + 64 + (half << 5) + woff);
        TC_WAIT_LD();
        const int col0 = 15 * 64 + (half << 5);
#pragma unroll
        for (int r = 0; r < 32; ++r) {
            int col = col0 + r;
            float d = __fadd_rn(rn, scn[col]) - 2.0f * __uint_as_float(regs[r]);
            if (d < m1)      { m2 = m1; m1 = d; i1 = col; }
            else if (d < m2) { m2 = d; }
            if (d <= m1 + MARGIN) {
                if (cnt < NC_H) cbase[cnt] = col;
                cnt++;
            }
        }
    }
    TC_FENCE_B();

    {
        float* blk = reinterpret_cast<float*>(sm + S_B) + (myrow * 2 + half) * 4;
        blk[0] = m1;
        reinterpret_cast<int*>(blk)[1] = i1;
        blk[2] = m2;
        reinterpret_cast<int*>(blk)[3] = cnt;
    }
    __syncthreads();
    if (half == 0) {
        float* A = reinterpret_cast<float*>(sm + S_B) + (myrow * 2) * 4;
        float* B = A + 4;
        float m1A = A[0], m2A = A[2], m1B = B[0], m2B = B[2];
        int i1A = reinterpret_cast<int*>(A)[1], i1B = reinterpret_cast<int*>(B)[1];
        int cA = reinterpret_cast<int*>(A)[3], cB = reinterpret_cast<int*>(B)[3];
        bool takeB = (m1B < m1A) || (m1B == m1A && i1B < i1A);
        float gm0 = takeB ? m1B : m1A;
        int   gi0 = takeB ? i1B : i1A;
        float second = fminf(takeB ? m1A : m1B, takeB ? m2B : m2A);
        g_idx[rowg] = gi0;
        if (cA > NC_H || cB > NC_H) g_ccount[rowg] = -1;
        else if (second > gm0 + MARGIN) g_ccount[rowg] = 0;
        else g_ccount[rowg] = cA | (cB << 8);
    }
    __syncthreads();
    if (tid == 0) { MBAR_INVAL(MB0); MBAR_INVAL(MB1); MBAR_INVAL(FB0); MBAR_INVAL(FB1); }
    __syncthreads();
    if (w == 0) { TC_RELINQ(); TC_DEALLOC(tmem, 512); }
#else
    int r = blockIdx.x * 128 + (int)threadIdx.x;
    if (threadIdx.x < 128) {
        float s = 0.f;
        for (int i = 0; i < DIMS; i++) { float v = g_z[(size_t)r * DIMS + i]; s += v * v; }
        g_rownorm[r] = s;
        g_idx[r] = 0;
        g_ccount[r] = -1;
    }
#endif
}

// ---------------- K4a: exact fp32 recheck of candidate lists -----------------
__global__ __launch_bounds__(256)
void recheck_kernel(const float* __restrict__ emb)
{
    int row  = blockIdx.x * 8 + (threadIdx.x >> 5);
    int lane = threadIdx.x & 31;
    int cc   = g_ccount[row];
    if (cc <= 0) return;
    int cntA = cc & 0xff, cntB = (cc >> 8) & 0xff;

    const float* zp = &g_z[(size_t)row * DIMS];
    float zv[8];
#pragma unroll
    for (int i = 0; i < 8; i++) zv[i] = zp[lane + 32 * i];
    float rn = g_rownorm[row];
    const int* cl = &g_cands[(size_t)row * CSTRIDE];

    float bv = CUDART_INF_F;
    int   bi = 0x7fffffff;
    for (int c = 0; c < cntA + cntB; c++) {
        int idx = (c < cntA) ? cl[c] : cl[NC_H + c - cntA];
        const float* ep = &emb[(size_t)idx * DIMS];
        float dot = 0.f;
#pragma unroll
        for (int i = 0; i < 8; i++) dot += zv[i] * ep[lane + 32 * i];
#pragma unroll
        for (int o = 16; o > 0; o >>= 1) dot += __shfl_down_sync(0xffffffffu, dot, o);
        if (lane == 0) {
            float t = __fadd_rn(rn, g_cnorm[idx]);
            float dist = __fadd_rn(t, -__fmul_rn(2.0f, dot));
            if (dist < bv || (dist == bv && idx < bi)) { bv = dist; bi = idx; }
        }
    }
    if (lane == 0) g_idx[row] = bi;
}

// ---------------- K4b: fast exact full scan for overflow rows (rare) ---------
__global__ __launch_bounds__(256)
void recheck_full_kernel(const float* __restrict__ emb)
{
    __shared__ float sz[DIMS];
    __shared__ float sv[256];
    __shared__ int   si[256];
    int t = threadIdx.x;
    for (int row = blockIdx.x * 16; row < blockIdx.x * 16 + 16; ++row) {
        if (g_ccount[row] != -1) continue;
        sz[t] = g_z[(size_t)row * DIMS + t];
        float rn = g_rownorm[row];
        __syncthreads();
        float best = CUDART_INF_F;
        int   bi = 0x7fffffff;
#pragma unroll
        for (int q = 0; q < 4; q++) {
            int c = q * 256 + t;
            const float* ep = &emb[(size_t)c * DIMS];
            float d0 = 0.f, d1 = 0.f, d2 = 0.f, d3 = 0.f;
#pragma unroll 8
            for (int i = 0; i < DIMS; i += 4) {
                d0 += sz[i+0] * ep[i+0];
                d1 += sz[i+1] * ep[i+1];
                d2 += sz[i+2] * ep[i+2];
                d3 += sz[i+3] * ep[i+3];
            }
            float dot = (d0 + d1) + (d2 + d3);
            float dist = __fadd_rn(__fadd_rn(rn, g_cnorm[c]), -__fmul_rn(2.0f, dot));
            if (dist < best || (dist == best && c < bi)) { best = dist; bi = c; }
        }
        sv[t] = best; si[t] = bi;
        __syncthreads();
        for (int o = 128; o > 0; o >>= 1) {
            if (t < o) {
                if (sv[t+o] < sv[t] || (sv[t+o] == sv[t] && si[t+o] < si[t])) {
                    sv[t] = sv[t+o]; si[t] = si[t+o];
                }
            }
            __syncthreads();
        }
        if (t == 0) g_idx[row] = si[0];
        __syncthreads();
    }
}

// ---------------- K5: gather + per-row loss -----------------------------------
__global__ void gather_kernel(const float* __restrict__ emb,
                              float* __restrict__ outq, float* __restrict__ outi)
{
    __shared__ float ws[8];
    int row = blockIdx.x, d = threadIdx.x;
    int idx = g_idx[row];
    float e = emb[(size_t)idx * DIMS + d];
    float z = g_z[(size_t)row * DIMS + d];
    outq[(size_t)row * DIMS + d] = e;
    float diff = e - z;
    float s = diff * diff;
#pragma unroll
    for (int o = 16; o > 0; o >>= 1) s += __shfl_down_sync(0xffffffffu, s, o);
    int lane = d & 31, w = d >> 5;
    if (lane == 0) ws[w] = s;
    __syncthreads();
    if (d == 0) {
        float tot = 0.f;
#pragma unroll
        for (int i = 0; i < 8; i++) tot += ws[i];
        g_rowloss[row] = tot;
        outi[row] = (float)idx;
    }
}

// ---------------- K6: loss reduction ------------------------------------------
__global__ void loss_kernel(float* __restrict__ outl)
{
    __shared__ double sd[256];
    double s = 0.0;
    for (int i = threadIdx.x; i < M_ROWS; i += 256) s += (double)g_rowloss[i];
    sd[threadIdx.x] = s;
    __syncthreads();
    for (int o = 128; o > 0; o >>= 1) {
        if (threadIdx.x < o) sd[threadIdx.x] += sd[threadIdx.x + o];
        __syncthreads();
    }
    if (threadIdx.x == 0) outl[0] = (float)(1.25 * sd[0] / 8388608.0);
}

// ---------------- host: tensormap setup + launch -------------------------------
typedef CUresult (*PFN_tmapenc)(CUtensorMap*, CUtensorMapDataType, cuuint32_t, void*,
                                const cuuint64_t*, const cuuint64_t*, const cuuint32_t*,
                                const cuuint32_t*, CUtensorMapInterleave, CUtensorMapSwizzle,
                                CUtensorMapL2promotion, CUtensorMapFloatOOBfill);
static CUtensorMap tm_eh, tm_el, tm_wh, tm_wm, tm_wl;

static void make_map(PFN_tmapenc enc, CUtensorMap* m, void* addr,
                     uint64_t d0, uint64_t d1, uint32_t b0, uint32_t b1)
{
    cuuint64_t dims[2] = {d0, d1};
    cuuint64_t strides[1] = {d0 * 2};
    cuuint32_t box[2] = {b0, b1};
    cuuint32_t es[2] = {1, 1};
    enc(m, CU_TENSOR_MAP_DATA_TYPE_BFLOAT16, 2, addr, dims, strides, box, es,
        CU_TENSOR_MAP_INTERLEAVE_NONE, CU_TENSOR_MAP_SWIZZLE_128B,
        CU_TENSOR_MAP_L2_PROMOTION_L2_128B, CU_TENSOR_MAP_FLOAT_OOB_FILL_NONE);
}

extern "C" void kernel_launch(void* const* d_in, const int* in_sizes, int n_in,
                              void* d_out, int out_size)
{
    const float* x   = (const float*)d_in[0];
    const float* W   = (const float*)d_in[1];
    const float* b   = (const float*)d_in[2];
    const float* emb = (const float*)d_in[3];

    float* out  = (float*)d_out;
    float* outq = out;
    float* outi = out + (size_t)M_ROWS * DIMS;
    float* outl = outi + M_ROWS;

    static int inited = 0;
    if (!inited) {
        cudaFuncSetAttribute(coarse_kernel, cudaFuncAttributeMaxDynamicSharedMemorySize, SMEM_NEED);
        cudaFuncSetAttribute(gemm_z_tc, cudaFuncAttributeMaxDynamicSharedMemorySize, GSMEM_NEED);
        void* fn = nullptr;
        cudaDriverEntryPointQueryResult qr;
        cudaGetDriverEntryPoint("cuTensorMapEncodeTiled", &fn, cudaEnableDefault, &qr);
        PFN_tmapenc enc = (PFN_tmapenc)fn;
        void *peh, *pel, *pwh, *pwm, *pwl;
        cudaGetSymbolAddress(&peh, g_eh);
        cudaGetSymbolAddress(&pel, g_el);
        cudaGetSymbolAddress(&pwh, g_wh);
        cudaGetSymbolAddress(&pwm, g_wm);
        cudaGetSymbolAddress(&pwl, g_wl);
        make_map(enc, &tm_eh, peh, 256, 1024, 64, 64);
        make_map(enc, &tm_el, pel, 256, 1024, 64, 64);
        make_map(enc, &tm_wh, pwh, 256, 256, 64, 256);
        make_map(enc, &tm_wm, pwm, 256, 256, 64, 256);
        make_map(enc, &tm_wl, pwl, 256, 256, 64, 256);
        inited = 1;
    }

    conv_w_kernel<<<32, 256>>>(W);
    conv_emb_kernel<<<NCODES / 8, 256>>>(emb);
    gemm_z_tc<<<M_ROWS / 128, 256, GSMEM_NEED>>>(x, W, b, tm_wh, tm_wm, tm_wl);
    coarse_kernel<<<M_ROWS / 128, 256, SMEM_NEED>>>(tm_eh, tm_el);
    recheck_kernel<<<M_ROWS / 8, 256>>>(emb);
    recheck_full_kernel<<<M_ROWS / 16, 256>>>(emb);
    gather_kernel<<<M_ROWS, 256>>>(emb, outq, outi);
    loss_kernel<<<1, 256>>>(outl);
}